// round 13
// baseline (speedup 1.0000x reference)
#include <cuda_runtime.h>
#include <math.h>
#include <stdint.h>

#define Bsz  4
#define Nseq 1024
#define Dmod 768
#define Hh   12
#define DHd  64
#define HID  3072
#define ROWS (Bsz*Nseq)   // 4096

// ---- scratch (no cudaMalloc allowed) ----
__device__ float g_h   [ROWS*Dmod];
__device__ float g_qkv [ROWS*3*Dmod];
__device__ float g_attn[ROWS*Dmod];
__device__ float g_x1  [ROWS*Dmod];
__device__ float g_h2  [ROWS*Dmod];
__device__ float g_act [ROWS*HID];
// transposed weights [N][K]
__device__ float g_wqkvT[3*Dmod*Dmod];
__device__ float g_wprojT[Dmod*Dmod];
__device__ float g_wfc1T[HID*Dmod];
__device__ float g_wfc2T[Dmod*HID];

__device__ __forceinline__ float round_tf32(float x) {
    unsigned r;
    asm("cvt.rna.tf32.f32 %0, %1;" : "=r"(r) : "f"(x));
    return __uint_as_float(r);
}

#define MMA_TF32(acc, a0,a1,a2,a3, b0,b1)                                   \
    asm volatile(                                                           \
        "mma.sync.aligned.m16n8k8.row.col.f32.tf32.tf32.f32 "               \
        "{%0,%1,%2,%3}, {%4,%5,%6,%7}, {%8,%9}, {%0,%1,%2,%3};"             \
        : "+f"(acc[0]), "+f"(acc[1]), "+f"(acc[2]), "+f"(acc[3])            \
        : "r"(a0), "r"(a1), "r"(a2), "r"(a3), "r"(b0), "r"(b1))

#define LDSM_X4(r, addr)                                                    \
    asm volatile("ldmatrix.sync.aligned.m8n8.x4.shared.b16 {%0,%1,%2,%3}, [%4];" \
        : "=r"((r)[0]), "=r"((r)[1]), "=r"((r)[2]), "=r"((r)[3]) : "r"(addr))

__device__ __forceinline__ void cp16(unsigned dst, const void* src) {
    asm volatile("cp.async.cg.shared.global [%0], [%1], 16;" :: "r"(dst), "l"(src));
}

// ---------------- weight transpose: [K][N] -> [N][K] ----------------
__global__ __launch_bounds__(256) void transpose32(
    const float* __restrict__ in, float* __restrict__ out, int K, int N)
{
    __shared__ float t[32][33];
    int n0 = blockIdx.x*32, k0 = blockIdx.y*32;
    int tx = threadIdx.x, ty = threadIdx.y;
#pragma unroll
    for (int i = 0; i < 4; i++)
        t[ty + i*8][tx] = in[(size_t)(k0 + ty + i*8)*N + n0 + tx];
    __syncthreads();
#pragma unroll
    for (int i = 0; i < 4; i++)
        out[(size_t)(n0 + ty + i*8)*K + k0 + tx] = t[tx][ty + i*8];
}

// ---------------- warp-per-row LayerNorm (tf32-rounded output) -------------
__global__ __launch_bounds__(256) void ln_warp(
    const float* __restrict__ x, const float* __restrict__ g,
    const float* __restrict__ b, float* __restrict__ out)
{
    const int warp = threadIdx.x >> 5, lane = threadIdx.x & 31;
    const int row  = blockIdx.x * 8 + warp;
    const float4* xr = (const float4*)(x + (size_t)row * Dmod);
    float4 v[6];
    float s = 0.f, s2 = 0.f;
#pragma unroll
    for (int i = 0; i < 6; i++) {
        v[i] = xr[lane + i*32];
        s  += v[i].x + v[i].y + v[i].z + v[i].w;
        s2 += v[i].x*v[i].x + v[i].y*v[i].y + v[i].z*v[i].z + v[i].w*v[i].w;
    }
#pragma unroll
    for (int off = 16; off; off >>= 1) {
        s  += __shfl_xor_sync(0xffffffffu, s,  off);
        s2 += __shfl_xor_sync(0xffffffffu, s2, off);
    }
    const float mu = s * (1.f/Dmod);
    const float rs = rsqrtf(s2 * (1.f/Dmod) - mu*mu + 1e-6f);
    float4* orow = (float4*)(out + (size_t)row * Dmod);
#pragma unroll
    for (int i = 0; i < 6; i++) {
        int c = lane + i*32;
        float4 gg = __ldg(&((const float4*)g)[c]);
        float4 bb = __ldg(&((const float4*)b)[c]);
        float4 o;
        o.x = round_tf32((v[i].x - mu)*rs*gg.x + bb.x);
        o.y = round_tf32((v[i].y - mu)*rs*gg.y + bb.y);
        o.z = round_tf32((v[i].z - mu)*rs*gg.z + bb.z);
        o.w = round_tf32((v[i].w - mu)*rs*gg.w + bb.w);
        orow[c] = o;
    }
}

// ---- tf32 GEMM: CTA tile 128x64, warp tile 64x16, 2-stage, 3 CTAs/SM -----
// A [M][K] row-major; WT [Nc][K] row-major (pre-transposed).
#define TS 36
#define STG64 (192*TS)                 // A(128*36) + B(64*36) floats per stage
#define GEMM_SMEM (2*STG64*4)          // 55296 B

template<bool GELU, bool RES, bool ROUND>
__global__ __launch_bounds__(256, 3) void gemm64(
    const float* __restrict__ A, const float* __restrict__ WT,
    const float* __restrict__ bias, const float* __restrict__ res,
    float* __restrict__ C, int M, int K, int Nc)
{
    extern __shared__ float sm[];

    const int tid  = threadIdx.x;
    const int lane = tid & 31;
    const int warp = tid >> 5;
    const int wm   = warp & 1;        // 0..1  (64 rows)
    const int wn   = warp >> 1;       // 0..3  (16 cols)
    const int bm   = blockIdx.y * 128;
    const int bn   = blockIdx.x * 64;

    float acc[4][2][4];
#pragma unroll
    for (int i = 0; i < 4; i++)
#pragma unroll
        for (int j = 0; j < 2; j++)
#pragma unroll
            for (int r = 0; r < 4; r++) acc[i][j][r] = 0.f;

    const int kTiles = K >> 5;

    auto load_stage = [&](int kt, int buf) {
        const int k0 = kt * 32;
        float* As = sm + buf*STG64;
        float* Bs = As + 128*TS;
#pragma unroll
        for (int i = 0; i < 4; i++) {              // A: 128 rows x 32 k
            int idx = tid + i*256;
            int r = idx >> 3, kk = (idx & 7) * 4;
            cp16((unsigned)__cvta_generic_to_shared(&As[r*TS + kk]),
                 A + (size_t)(bm + r) * K + k0 + kk);
        }
#pragma unroll
        for (int i = 0; i < 2; i++) {              // B: 64 rows x 32 k
            int idx = tid + i*256;
            int r = idx >> 3, kk = (idx & 7) * 4;
            cp16((unsigned)__cvta_generic_to_shared(&Bs[r*TS + kk]),
                 WT + (size_t)(bn + r) * K + k0 + kk);
        }
        asm volatile("cp.async.commit_group;");
    };

    load_stage(0, 0);

    const int r8 = lane >> 2;
    const int c4 = lane & 3;
    const int lrow  = ((lane >> 3) & 1) * 8 + (lane & 7);
    const int lcol  = (lane >> 4) * 4;
    const int kprow = ((lane >> 4) & 1) * 8 + (lane & 7);
    const int kpcol = ((lane >> 3) & 1) * 4;

    const uint32_t a_base = ((wm*64 + lrow)*TS + lcol) * 4u;
    const uint32_t b_base = ((wn*16 + kprow)*TS + kpcol) * 4u;
    const uint32_t sm_u32 = (uint32_t)__cvta_generic_to_shared(sm);

    for (int kt = 0; kt < kTiles; kt++) {
        asm volatile("cp.async.wait_group 0;");
        __syncthreads();
        if (kt + 1 < kTiles) load_stage(kt + 1, (kt + 1) & 1);

        const uint32_t as_u32 = sm_u32 + (kt & 1)*STG64*4u;
        const uint32_t bs_u32 = as_u32 + 128*TS*4u;
#pragma unroll
        for (int k8 = 0; k8 < 4; k8++) {
            unsigned af[4][4], bf[4];
#pragma unroll
            for (int mt = 0; mt < 4; mt++)
                LDSM_X4(af[mt], as_u32 + a_base + mt*(16u*TS*4u) + k8*32u);
            LDSM_X4(bf, bs_u32 + b_base + k8*32u);
#pragma unroll
            for (int mt = 0; mt < 4; mt++) {
                MMA_TF32(acc[mt][0], af[mt][0], af[mt][1], af[mt][2], af[mt][3],
                         bf[0], bf[1]);
                MMA_TF32(acc[mt][1], af[mt][0], af[mt][1], af[mt][2], af[mt][3],
                         bf[2], bf[3]);
            }
        }
    }

    // ---- epilogue ----
#pragma unroll
    for (int mt = 0; mt < 4; mt++) {
        int row0 = bm + wm*64 + mt*16 + r8;
#pragma unroll
        for (int nt = 0; nt < 2; nt++) {
            int col0 = bn + wn*16 + nt*8 + c4*2;
            float b0 = __ldg(&bias[col0]), b1 = __ldg(&bias[col0 + 1]);
#pragma unroll
            for (int half = 0; half < 2; half++) {
                int row = row0 + half*8;
                float v0 = acc[mt][nt][half*2 + 0] + b0;
                float v1 = acc[mt][nt][half*2 + 1] + b1;
                if (GELU) { v0 = v0 * normcdff(v0); v1 = v1 * normcdff(v1); }
                if (RES) {
                    const float2 rr = *(const float2*)&res[(size_t)row*Nc + col0];
                    v0 += rr.x; v1 += rr.y;
                }
                if (ROUND) { v0 = round_tf32(v0); v1 = round_tf32(v1); }
                *(float2*)&C[(size_t)row*Nc + col0] = make_float2(v0, v1);
            }
        }
    }
}

// ------- Tensor-core flash attention: cp.async double-buffer, no P smem ----
#define QP_STR 68
#define V_STR  72

__global__ __launch_bounds__(256) void attn_tc(
    const float* __restrict__ qkv, const float* __restrict__ adj,
    float* __restrict__ out)
{
    extern __shared__ float sma[];
    float* Qs  = sma;
    float* Kb0 = Qs + 128*QP_STR;
    float* Vb0 = Kb0 + 2*64*QP_STR;

    const int tid  = threadIdx.x;
    const int lane = tid & 31;
    const int warp = tid >> 5;
    const int r8   = lane >> 2;
    const int c4   = lane & 3;
    const int bh   = blockIdx.y;
    const int b    = bh / Hh, h = bh % Hh;
    const int q0   = blockIdx.x * 128;
    const int qrow = (warp >> 2)*64 + (warp & 3)*16;
    const float scale = 0.125f;

    const int lrow  = ((lane >> 3) & 1) * 8 + (lane & 7);
    const int lcol  = (lane >> 4) * 4;
    const int kprow = ((lane >> 4) & 1) * 8 + (lane & 7);
    const int kpcol = ((lane >> 3) & 1) * 4;

    const uint32_t qs_u32 = (uint32_t)__cvta_generic_to_shared(Qs);
    uint32_t ks_u32[2] = {
        (uint32_t)__cvta_generic_to_shared(Kb0),
        (uint32_t)__cvta_generic_to_shared(Kb0 + 64*QP_STR) };
    float* Vbuf[2] = { Vb0, Vb0 + 64*V_STR };
    const uint32_t q_off  = ((qrow + lrow)*QP_STR + lcol) * 4u;
    const uint32_t kp_off = (kprow*QP_STR + kpcol) * 4u;

#pragma unroll
    for (int it = 0; it < 32; it++) {
        int idx = tid + it*256;
        int r = idx >> 6, d = idx & 63;
        Qs[r*QP_STR + d] = qkv[(size_t)(b*Nseq + q0 + r)*(3*Dmod) + h*DHd + d];
    }

    auto load_kv = [&](int kt, int buf) {
        const int k0 = kt*64;
        float* kd = Kb0 + buf*64*QP_STR;
        float* vd = Vbuf[buf];
#pragma unroll
        for (int i = 0; i < 4; i++) {
            int idx = tid + i*256;
            int r = idx >> 4, d4 = (idx & 15) * 4;
            size_t base = (size_t)(b*Nseq + k0 + r)*(3*Dmod) + h*DHd + d4;
            cp16((unsigned)__cvta_generic_to_shared(&kd[r*QP_STR + d4]),
                 qkv + base + Dmod);
            cp16((unsigned)__cvta_generic_to_shared(&vd[r*V_STR + d4]),
                 qkv + base + 2*Dmod);
        }
        asm volatile("cp.async.commit_group;");
    };

    load_kv(0, 0);

    float m0 = -1e30f, m1 = -1e30f, l0 = 0.f, l1 = 0.f;
    float o[8][4];
#pragma unroll
    for (int nt = 0; nt < 8; nt++)
#pragma unroll
        for (int r = 0; r < 4; r++) o[nt][r] = 0.f;

    const int srcA = (lane & ~3) | (c4 >> 1);
    const int srcB = srcA + 2;
    const bool oddc = c4 & 1;

    for (int kt = 0; kt < Nseq/64; kt++) {
        const int buf = kt & 1;
        asm volatile("cp.async.wait_group 0;");
        __syncthreads();
        if (kt + 1 < Nseq/64) load_kv(kt + 1, buf ^ 1);

        float s[8][4];
#pragma unroll
        for (int nt = 0; nt < 8; nt++)
#pragma unroll
            for (int r = 0; r < 4; r++) s[nt][r] = 0.f;

#pragma unroll
        for (int k8 = 0; k8 < 8; k8++) {
            unsigned aq[4];
            LDSM_X4(aq, qs_u32 + q_off + k8*32u);
#pragma unroll
            for (int ntp = 0; ntp < 4; ntp++) {
                unsigned kb4[4];
                LDSM_X4(kb4, ks_u32[buf] + kp_off + ntp*(16u*QP_STR*4u) + k8*32u);
                MMA_TF32(s[2*ntp    ], aq[0], aq[1], aq[2], aq[3], kb4[0], kb4[1]);
                MMA_TF32(s[2*ntp + 1], aq[0], aq[1], aq[2], aq[3], kb4[2], kb4[3]);
            }
        }

        const int k0 = kt*64;
        const int qg0 = q0 + qrow + r8;
#pragma unroll
        for (int nt = 0; nt < 8; nt++) {
            int col = k0 + nt*8 + c4*2;
            float2 ad0 = *(const float2*)&adj[(size_t) qg0     *Nseq + col];
            float2 ad1 = *(const float2*)&adj[(size_t)(qg0 + 8)*Nseq + col];
            s[nt][0] = s[nt][0]*scale + ad0.x;
            s[nt][1] = s[nt][1]*scale + ad0.y;
            s[nt][2] = s[nt][2]*scale + ad1.x;
            s[nt][3] = s[nt][3]*scale + ad1.y;
        }

        float mx0 = -1e30f, mx1 = -1e30f;
#pragma unroll
        for (int nt = 0; nt < 8; nt++) {
            mx0 = fmaxf(mx0, fmaxf(s[nt][0], s[nt][1]));
            mx1 = fmaxf(mx1, fmaxf(s[nt][2], s[nt][3]));
        }
        mx0 = fmaxf(mx0, __shfl_xor_sync(0xffffffffu, mx0, 1));
        mx0 = fmaxf(mx0, __shfl_xor_sync(0xffffffffu, mx0, 2));
        mx1 = fmaxf(mx1, __shfl_xor_sync(0xffffffffu, mx1, 1));
        mx1 = fmaxf(mx1, __shfl_xor_sync(0xffffffffu, mx1, 2));
        float mn0 = fmaxf(m0, mx0), mn1 = fmaxf(m1, mx1);
        float al0 = __expf(m0 - mn0), al1 = __expf(m1 - mn1);
        float rs0 = 0.f, rs1 = 0.f;
#pragma unroll
        for (int nt = 0; nt < 8; nt++) {
            s[nt][0] = __expf(s[nt][0] - mn0);
            s[nt][1] = __expf(s[nt][1] - mn0);
            s[nt][2] = __expf(s[nt][2] - mn1);
            s[nt][3] = __expf(s[nt][3] - mn1);
            rs0 += s[nt][0] + s[nt][1];
            rs1 += s[nt][2] + s[nt][3];
        }
        rs0 += __shfl_xor_sync(0xffffffffu, rs0, 1);
        rs0 += __shfl_xor_sync(0xffffffffu, rs0, 2);
        rs1 += __shfl_xor_sync(0xffffffffu, rs1, 1);
        rs1 += __shfl_xor_sync(0xffffffffu, rs1, 2);
        l0 = l0*al0 + rs0;  l1 = l1*al1 + rs1;
        m0 = mn0;           m1 = mn1;
#pragma unroll
        for (int nt = 0; nt < 8; nt++) {
            o[nt][0] *= al0; o[nt][1] *= al0;
            o[nt][2] *= al1; o[nt][3] *= al1;
        }

        const float* vs = Vbuf[buf];
#pragma unroll
        for (int k8 = 0; k8 < 8; k8++) {
            const int kb = k8*8;
            float t0 = __shfl_sync(0xffffffffu, s[k8][0], srcA);
            float t1 = __shfl_sync(0xffffffffu, s[k8][1], srcA);
            float t2 = __shfl_sync(0xffffffffu, s[k8][2], srcA);
            float t3 = __shfl_sync(0xffffffffu, s[k8][3], srcA);
            float u0 = __shfl_sync(0xffffffffu, s[k8][0], srcB);
            float u1 = __shfl_sync(0xffffffffu, s[k8][1], srcB);
            float u2 = __shfl_sync(0xffffffffu, s[k8][2], srcB);
            float u3 = __shfl_sync(0xffffffffu, s[k8][3], srcB);
            unsigned ap0 = __float_as_uint(oddc ? t1 : t0);
            unsigned ap1 = __float_as_uint(oddc ? t3 : t2);
            unsigned ap2 = __float_as_uint(oddc ? u1 : u0);
            unsigned ap3 = __float_as_uint(oddc ? u3 : u2);
#pragma unroll
            for (int nt = 0; nt < 8; nt++) {
                unsigned b0 = __float_as_uint(vs[(kb + c4    )*V_STR + nt*8 + r8]);
                unsigned b1 = __float_as_uint(vs[(kb + c4 + 4)*V_STR + nt*8 + r8]);
                MMA_TF32(o[nt], ap0, ap1, ap2, ap3, b0, b1);
            }
        }
        __syncthreads();
    }

    const int qg0 = q0 + qrow + r8;
    float i0 = 1.f / l0, i1 = 1.f / l1;
#pragma unroll
    for (int nt = 0; nt < 8; nt++) {
        int col = h*DHd + nt*8 + c4*2;
        *(float2*)&out[(size_t)(b*Nseq + qg0    )*Dmod + col] =
            make_float2(round_tf32(o[nt][0]*i0), round_tf32(o[nt][1]*i0));
        *(float2*)&out[(size_t)(b*Nseq + qg0 + 8)*Dmod + col] =
            make_float2(round_tf32(o[nt][2]*i1), round_tf32(o[nt][3]*i1));
    }
}

// ---------------- launcher ----------------
extern "C" void kernel_launch(void* const* d_in, const int* in_sizes, int n_in,
                              void* d_out, int out_size)
{
    const float* x      = (const float*)d_in[0];
    const float* adj    = (const float*)d_in[1];
    const float* ln1_g  = (const float*)d_in[2];
    const float* ln1_b  = (const float*)d_in[3];
    const float* qkv_w  = (const float*)d_in[4];
    const float* qkv_b  = (const float*)d_in[5];
    const float* proj_w = (const float*)d_in[6];
    const float* proj_b = (const float*)d_in[7];
    const float* ln2_g  = (const float*)d_in[8];
    const float* ln2_b  = (const float*)d_in[9];
    const float* fc1_w  = (const float*)d_in[10];
    const float* fc1_b  = (const float*)d_in[11];
    const float* fc2_w  = (const float*)d_in[12];
    const float* fc2_b  = (const float*)d_in[13];
    float* out = (float*)d_out;

    float *h, *qkv, *attn, *x1, *h2, *act;
    float *wqkvT, *wprojT, *wfc1T, *wfc2T;
    cudaGetSymbolAddress((void**)&h,     g_h);
    cudaGetSymbolAddress((void**)&qkv,   g_qkv);
    cudaGetSymbolAddress((void**)&attn,  g_attn);
    cudaGetSymbolAddress((void**)&x1,    g_x1);
    cudaGetSymbolAddress((void**)&h2,    g_h2);
    cudaGetSymbolAddress((void**)&act,   g_act);
    cudaGetSymbolAddress((void**)&wqkvT, g_wqkvT);
    cudaGetSymbolAddress((void**)&wprojT,g_wprojT);
    cudaGetSymbolAddress((void**)&wfc1T, g_wfc1T);
    cudaGetSymbolAddress((void**)&wfc2T, g_wfc2T);

    const int attn_smem = (128*QP_STR + 2*64*QP_STR + 2*64*V_STR)
                          * sizeof(float);   // 106496 B
    static cudaStream_t s2 = nullptr;
    static cudaEvent_t evA = nullptr, evQ = nullptr, evW = nullptr;
    if (!s2) {
        cudaFuncSetAttribute(gemm64<false,false,false>,
            cudaFuncAttributeMaxDynamicSharedMemorySize, GEMM_SMEM);
        cudaFuncSetAttribute(gemm64<false,true,false>,
            cudaFuncAttributeMaxDynamicSharedMemorySize, GEMM_SMEM);
        cudaFuncSetAttribute(gemm64<true,false,true>,
            cudaFuncAttributeMaxDynamicSharedMemorySize, GEMM_SMEM);
        cudaFuncSetAttribute(attn_tc,
            cudaFuncAttributeMaxDynamicSharedMemorySize, attn_smem);
        cudaStreamCreateWithFlags(&s2, cudaStreamNonBlocking);
        cudaEventCreateWithFlags(&evA, cudaEventDisableTiming);
        cudaEventCreateWithFlags(&evQ, cudaEventDisableTiming);
        cudaEventCreateWithFlags(&evW, cudaEventDisableTiming);
    }

    dim3 tb(32, 8);

    // ---- fork: side stream does all weight transposes ----
    cudaEventRecord(evA, 0);
    cudaStreamWaitEvent(s2, evA, 0);
    transpose32<<<dim3(3*Dmod/32, Dmod/32), tb, 0, s2>>>(qkv_w, wqkvT, Dmod, 3*Dmod);
    cudaEventRecord(evQ, s2);
    transpose32<<<dim3(Dmod/32, Dmod/32), tb, 0, s2>>>(proj_w, wprojT, Dmod, Dmod);
    transpose32<<<dim3(HID/32,  Dmod/32), tb, 0, s2>>>(fc1_w,  wfc1T, Dmod, HID);
    transpose32<<<dim3(Dmod/32, HID/32),  tb, 0, s2>>>(fc2_w,  wfc2T, HID, Dmod);
    cudaEventRecord(evW, s2);

    // ---- main stream ----
    ln_warp<<<ROWS/8, 256>>>(x, ln1_g, ln1_b, h);
    cudaStreamWaitEvent(0, evQ, 0);
    // qkv = h @ qkv_w + qkv_b          grid (36, 32)
    gemm64<false,false,false><<<dim3(3*Dmod/64, ROWS/128), 256, GEMM_SMEM>>>(
        h, wqkvT, qkv_b, nullptr, qkv, ROWS, Dmod, 3*Dmod);
    // attention
    attn_tc<<<dim3(Nseq/128, Bsz*Hh), 256, attn_smem>>>(qkv, adj, attn);
    cudaStreamWaitEvent(0, evW, 0);
    // x1 = x + attn @ proj_w + proj_b  grid (12, 32), no split-K
    gemm64<false,true,false><<<dim3(Dmod/64, ROWS/128), 256, GEMM_SMEM>>>(
        attn, wprojT, proj_b, x, x1, ROWS, Dmod, Dmod);
    // LN2
    ln_warp<<<ROWS/8, 256>>>(x1, ln2_g, ln2_b, h2);
    // act = gelu(h2 @ fc1_w + fc1_b)   grid (48, 32)
    gemm64<true,false,true><<<dim3(HID/64, ROWS/128), 256, GEMM_SMEM>>>(
        h2, wfc1T, fc1_b, nullptr, act, ROWS, Dmod, HID);
    // out = x1 + act @ fc2_w + fc2_b   grid (12, 32), no split-K
    gemm64<false,true,false><<<dim3(Dmod/64, ROWS/128), 256, GEMM_SMEM>>>(
        act, wfc2T, fc2_b, x1, out, ROWS, HID, Dmod);
}

// round 14
// speedup vs baseline: 1.1205x; 1.1205x over previous
#include <cuda_runtime.h>
#include <math.h>
#include <stdint.h>

#define Bsz  4
#define Nseq 1024
#define Dmod 768
#define Hh   12
#define DHd  64
#define HID  3072
#define ROWS (Bsz*Nseq)   // 4096

// ---- scratch (no cudaMalloc allowed) ----
__device__ float g_h   [ROWS*Dmod];
__device__ float g_qkv [ROWS*3*Dmod];
__device__ float g_attn[ROWS*Dmod];
__device__ float g_x1  [ROWS*Dmod];
__device__ float g_h2  [ROWS*Dmod];
__device__ float g_act [ROWS*HID];
__device__ float g_part[3*ROWS*Dmod];   // split-K partials
// transposed weights [N][K]
__device__ float g_wqkvT[3*Dmod*Dmod];
__device__ float g_wprojT[Dmod*Dmod];
__device__ float g_wfc1T[HID*Dmod];
__device__ float g_wfc2T[Dmod*HID];

__device__ __forceinline__ float round_tf32(float x) {
    unsigned r;
    asm("cvt.rna.tf32.f32 %0, %1;" : "=r"(r) : "f"(x));
    return __uint_as_float(r);
}

#define MMA_TF32(acc, a0,a1,a2,a3, b0,b1)                                   \
    asm volatile(                                                           \
        "mma.sync.aligned.m16n8k8.row.col.f32.tf32.tf32.f32 "               \
        "{%0,%1,%2,%3}, {%4,%5,%6,%7}, {%8,%9}, {%0,%1,%2,%3};"             \
        : "+f"(acc[0]), "+f"(acc[1]), "+f"(acc[2]), "+f"(acc[3])            \
        : "r"(a0), "r"(a1), "r"(a2), "r"(a3), "r"(b0), "r"(b1))

#define LDSM_X4(r, addr)                                                    \
    asm volatile("ldmatrix.sync.aligned.m8n8.x4.shared.b16 {%0,%1,%2,%3}, [%4];" \
        : "=r"((r)[0]), "=r"((r)[1]), "=r"((r)[2]), "=r"((r)[3]) : "r"(addr))

__device__ __forceinline__ void cp16(unsigned dst, const void* src) {
    asm volatile("cp.async.cg.shared.global [%0], [%1], 16;" :: "r"(dst), "l"(src));
}

// ---------------- weight transpose: [K][N] -> [N][K] ----------------
__global__ __launch_bounds__(256) void transpose32(
    const float* __restrict__ in, float* __restrict__ out, int K, int N)
{
    __shared__ float t[32][33];
    int n0 = blockIdx.x*32, k0 = blockIdx.y*32;
    int tx = threadIdx.x, ty = threadIdx.y;
#pragma unroll
    for (int i = 0; i < 4; i++)
        t[ty + i*8][tx] = in[(size_t)(k0 + ty + i*8)*N + n0 + tx];
    __syncthreads();
#pragma unroll
    for (int i = 0; i < 4; i++)
        out[(size_t)(n0 + ty + i*8)*K + k0 + tx] = t[tx][ty + i*8];
}

// ---------------- warp-per-row LayerNorm (tf32-rounded output) -------------
__global__ __launch_bounds__(256) void ln_warp(
    const float* __restrict__ x, const float* __restrict__ g,
    const float* __restrict__ b, float* __restrict__ out)
{
    const int warp = threadIdx.x >> 5, lane = threadIdx.x & 31;
    const int row  = blockIdx.x * 8 + warp;
    const float4* xr = (const float4*)(x + (size_t)row * Dmod);
    float4 v[6];
    float s = 0.f, s2 = 0.f;
#pragma unroll
    for (int i = 0; i < 6; i++) {
        v[i] = xr[lane + i*32];
        s  += v[i].x + v[i].y + v[i].z + v[i].w;
        s2 += v[i].x*v[i].x + v[i].y*v[i].y + v[i].z*v[i].z + v[i].w*v[i].w;
    }
#pragma unroll
    for (int off = 16; off; off >>= 1) {
        s  += __shfl_xor_sync(0xffffffffu, s,  off);
        s2 += __shfl_xor_sync(0xffffffffu, s2, off);
    }
    const float mu = s * (1.f/Dmod);
    const float rs = rsqrtf(s2 * (1.f/Dmod) - mu*mu + 1e-6f);
    float4* orow = (float4*)(out + (size_t)row * Dmod);
#pragma unroll
    for (int i = 0; i < 6; i++) {
        int c = lane + i*32;
        float4 gg = __ldg(&((const float4*)g)[c]);
        float4 bb = __ldg(&((const float4*)b)[c]);
        float4 o;
        o.x = round_tf32((v[i].x - mu)*rs*gg.x + bb.x);
        o.y = round_tf32((v[i].y - mu)*rs*gg.y + bb.y);
        o.z = round_tf32((v[i].z - mu)*rs*gg.z + bb.z);
        o.w = round_tf32((v[i].w - mu)*rs*gg.w + bb.w);
        orow[c] = o;
    }
}

// ------- fused split-K reduce + residual + LN: x1 and h2 in one pass -------
__global__ __launch_bounds__(256) void reduce3_ln(
    const float* __restrict__ p, const float* __restrict__ bias,
    const float* __restrict__ res, float* __restrict__ x1,
    const float* __restrict__ g, const float* __restrict__ bv,
    float* __restrict__ h2)
{
    const int warp = threadIdx.x >> 5, lane = threadIdx.x & 31;
    const int row  = blockIdx.x * 8 + warp;
    const size_t tot4 = (size_t)ROWS * Dmod / 4;
    const size_t base4 = (size_t)row * (Dmod/4);
    float4 v[6];
    float s = 0.f, s2 = 0.f;
#pragma unroll
    for (int i = 0; i < 6; i++) {
        int c = lane + i*32;
        size_t idx = base4 + c;
        float4 a  = ((const float4*)p)[idx];
        float4 b2 = ((const float4*)p)[idx + tot4];
        float4 c2 = ((const float4*)p)[idx + 2*tot4];
        float4 r  = ((const float4*)res)[idx];
        float4 bi = __ldg(&((const float4*)bias)[c]);
        float4 o;
        o.x = a.x + b2.x + c2.x + bi.x + r.x;
        o.y = a.y + b2.y + c2.y + bi.y + r.y;
        o.z = a.z + b2.z + c2.z + bi.z + r.z;
        o.w = a.w + b2.w + c2.w + bi.w + r.w;
        ((float4*)x1)[idx] = o;
        v[i] = o;
        s  += o.x + o.y + o.z + o.w;
        s2 += o.x*o.x + o.y*o.y + o.z*o.z + o.w*o.w;
    }
#pragma unroll
    for (int off = 16; off; off >>= 1) {
        s  += __shfl_xor_sync(0xffffffffu, s,  off);
        s2 += __shfl_xor_sync(0xffffffffu, s2, off);
    }
    const float mu = s * (1.f/Dmod);
    const float rs = rsqrtf(s2 * (1.f/Dmod) - mu*mu + 1e-6f);
#pragma unroll
    for (int i = 0; i < 6; i++) {
        int c = lane + i*32;
        float4 gg = __ldg(&((const float4*)g)[c]);
        float4 bb = __ldg(&((const float4*)bv)[c]);
        float4 o;
        o.x = round_tf32((v[i].x - mu)*rs*gg.x + bb.x);
        o.y = round_tf32((v[i].y - mu)*rs*gg.y + bb.y);
        o.z = round_tf32((v[i].z - mu)*rs*gg.z + bb.z);
        o.w = round_tf32((v[i].w - mu)*rs*gg.w + bb.w);
        ((float4*)h2)[base4 + c] = o;
    }
}

// ---------------- split-K reduction: out = p0+p1+p2 + bias + res ----------
__global__ __launch_bounds__(256) void reduce3_kernel(
    const float* __restrict__ p, const float* __restrict__ bias,
    const float* __restrict__ res, float* __restrict__ out, int Nc)
{
    int i = blockIdx.x * 256 + threadIdx.x;
    const size_t tot = (size_t)ROWS * Nc;
    float4 a = ((const float4*)p)[i];
    float4 b = ((const float4*)(p + tot))[i];
    float4 c = ((const float4*)(p + 2*tot))[i];
    float4 r = ((const float4*)res)[i];
    int col = (i*4) % Nc;
    const float4 bi = *(const float4*)&bias[col];
    float4 o;
    o.x = a.x + b.x + c.x + bi.x + r.x;
    o.y = a.y + b.y + c.y + bi.y + r.y;
    o.z = a.z + b.z + c.z + bi.z + r.z;
    o.w = a.w + b.w + c.w + bi.w + r.w;
    ((float4*)out)[i] = o;
}

// --------- tf32 GEMM 128x128, 3-stage, full-LDSM (W pre-transposed) --------
#define TS 36
#define STAGE_FLOATS (2*128*TS)
#define GEMM_SMEM (3*STAGE_FLOATS*4)

template<bool GELU, bool RES, bool ROUND, bool PARTIAL>
__global__ __launch_bounds__(256, 2) void gemm_tc(
    const float* __restrict__ A, const float* __restrict__ WT,
    const float* __restrict__ bias, const float* __restrict__ res,
    float* __restrict__ C, int M, int Kfull, int Nc, int Ks)
{
    extern __shared__ float sm[];

    const int tid  = threadIdx.x;
    const int lane = tid & 31;
    const int warp = tid >> 5;
    const int wm   = warp & 1;
    const int wn   = warp >> 1;
    const int bm   = blockIdx.y * 128;
    const int bn   = blockIdx.x * 128;
    const int z    = blockIdx.z;

    const float* Ab = A  + (size_t)z * Ks;
    const float* Wb = WT + (size_t)z * Ks;
    float* Cb = PARTIAL ? (C + (size_t)z * M * Nc) : C;

    float acc[4][4][4];
#pragma unroll
    for (int i = 0; i < 4; i++)
#pragma unroll
        for (int j = 0; j < 4; j++)
#pragma unroll
            for (int r = 0; r < 4; r++) acc[i][j][r] = 0.f;

    const int kTiles = Ks >> 5;

    auto load_stage = [&](int kt, int buf) {
        const int k0 = kt * 32;
        float* As = sm + buf*STAGE_FLOATS;
        float* Bs = As + 128*TS;
#pragma unroll
        for (int i = 0; i < 4; i++) {
            int idx = tid + i*256;
            int r = idx >> 3, kk = (idx & 7) * 4;
            cp16((unsigned)__cvta_generic_to_shared(&As[r*TS + kk]),
                 Ab + (size_t)(bm + r) * Kfull + k0 + kk);
        }
#pragma unroll
        for (int i = 0; i < 4; i++) {
            int idx = tid + i*256;
            int r = idx >> 3, kk = (idx & 7) * 4;
            cp16((unsigned)__cvta_generic_to_shared(&Bs[r*TS + kk]),
                 Wb + (size_t)(bn + r) * Kfull + k0 + kk);
        }
        asm volatile("cp.async.commit_group;");
    };

    load_stage(0, 0);
    load_stage(1, 1);

    const int r8 = lane >> 2;
    const int c4 = lane & 3;
    const int lrow = ((lane >> 3) & 1) * 8 + (lane & 7);
    const int lcol = (lane >> 4) * 4;
    const int kprow = ((lane >> 4) & 1) * 8 + (lane & 7);
    const int kpcol = ((lane >> 3) & 1) * 4;

    const uint32_t a_base = ((wm*64 + lrow)*TS + lcol) * 4u;
    const uint32_t b_base = ((wn*32 + kprow)*TS + kpcol) * 4u;

    for (int kt = 0; kt < kTiles; kt++) {
        if (kt + 1 < kTiles) asm volatile("cp.async.wait_group 1;");
        else                 asm volatile("cp.async.wait_group 0;");
        __syncthreads();
        if (kt + 2 < kTiles) load_stage(kt + 2, (kt + 2) % 3);

        const int buf = kt % 3;
        const uint32_t as_u32 = (uint32_t)__cvta_generic_to_shared(sm)
                                + buf*STAGE_FLOATS*4u;
        const uint32_t bs_u32 = as_u32 + 128*TS*4u;
#pragma unroll
        for (int k8 = 0; k8 < 4; k8++) {
            unsigned af[4][4], bf[2][4];
#pragma unroll
            for (int mt = 0; mt < 4; mt++)
                LDSM_X4(af[mt], as_u32 + a_base + mt*(16u*TS*4u) + k8*32u);
#pragma unroll
            for (int p = 0; p < 2; p++)
                LDSM_X4(bf[p], bs_u32 + b_base + p*(16u*TS*4u) + k8*32u);
#pragma unroll
            for (int mt = 0; mt < 4; mt++) {
                MMA_TF32(acc[mt][0], af[mt][0], af[mt][1], af[mt][2], af[mt][3],
                         bf[0][0], bf[0][1]);
                MMA_TF32(acc[mt][1], af[mt][0], af[mt][1], af[mt][2], af[mt][3],
                         bf[0][2], bf[0][3]);
                MMA_TF32(acc[mt][2], af[mt][0], af[mt][1], af[mt][2], af[mt][3],
                         bf[1][0], bf[1][1]);
                MMA_TF32(acc[mt][3], af[mt][0], af[mt][1], af[mt][2], af[mt][3],
                         bf[1][2], bf[1][3]);
            }
        }
    }

#pragma unroll
    for (int mt = 0; mt < 4; mt++) {
        int row0 = bm + wm*64 + mt*16 + r8;
#pragma unroll
        for (int nt = 0; nt < 4; nt++) {
            int col0 = bn + wn*32 + nt*8 + c4*2;
            float b0 = 0.f, b1 = 0.f;
            if (!PARTIAL) { b0 = __ldg(&bias[col0]); b1 = __ldg(&bias[col0 + 1]); }
#pragma unroll
            for (int half = 0; half < 2; half++) {
                int row = row0 + half*8;
                float v0 = acc[mt][nt][half*2 + 0] + b0;
                float v1 = acc[mt][nt][half*2 + 1] + b1;
                if (GELU) { v0 = v0 * normcdff(v0); v1 = v1 * normcdff(v1); }
                if (RES) {
                    const float2 rr = *(const float2*)&res[(size_t)row*Nc + col0];
                    v0 += rr.x; v1 += rr.y;
                }
                if (ROUND) { v0 = round_tf32(v0); v1 = round_tf32(v1); }
                *(float2*)&Cb[(size_t)row*Nc + col0] = make_float2(v0, v1);
            }
        }
    }
}

// ------- Tensor-core flash attention: cp.async double-buffer, no P smem ----
#define QP_STR 68
#define V_STR  72

__global__ __launch_bounds__(256) void attn_tc(
    const float* __restrict__ qkv, const float* __restrict__ adj,
    float* __restrict__ out)
{
    extern __shared__ float sma[];
    float* Qs  = sma;
    float* Kb0 = Qs + 128*QP_STR;
    float* Vb0 = Kb0 + 2*64*QP_STR;

    const int tid  = threadIdx.x;
    const int lane = tid & 31;
    const int warp = tid >> 5;
    const int r8   = lane >> 2;
    const int c4   = lane & 3;
    const int bh   = blockIdx.y;
    const int b    = bh / Hh, h = bh % Hh;
    const int q0   = blockIdx.x * 128;
    const int qrow = (warp >> 2)*64 + (warp & 3)*16;
    const float scale = 0.125f;

    const int lrow  = ((lane >> 3) & 1) * 8 + (lane & 7);
    const int lcol  = (lane >> 4) * 4;
    const int kprow = ((lane >> 4) & 1) * 8 + (lane & 7);
    const int kpcol = ((lane >> 3) & 1) * 4;

    const uint32_t qs_u32 = (uint32_t)__cvta_generic_to_shared(Qs);
    uint32_t ks_u32[2] = {
        (uint32_t)__cvta_generic_to_shared(Kb0),
        (uint32_t)__cvta_generic_to_shared(Kb0 + 64*QP_STR) };
    float* Vbuf[2] = { Vb0, Vb0 + 64*V_STR };
    const uint32_t q_off  = ((qrow + lrow)*QP_STR + lcol) * 4u;
    const uint32_t kp_off = (kprow*QP_STR + kpcol) * 4u;

    // load Q tile vectorized: 128 rows x 16 float4
#pragma unroll
    for (int it = 0; it < 8; it++) {
        int idx = tid + it*256;
        int r = idx >> 4, d4 = (idx & 15) * 4;
        float4 q4 = *(const float4*)&qkv[(size_t)(b*Nseq + q0 + r)*(3*Dmod)
                                         + h*DHd + d4];
        *(float4*)&Qs[r*QP_STR + d4] = q4;
    }

    auto load_kv = [&](int kt, int buf) {
        const int k0 = kt*64;
        float* kd = Kb0 + buf*64*QP_STR;
        float* vd = Vbuf[buf];
#pragma unroll
        for (int i = 0; i < 4; i++) {
            int idx = tid + i*256;
            int r = idx >> 4, d4 = (idx & 15) * 4;
            size_t base = (size_t)(b*Nseq + k0 + r)*(3*Dmod) + h*DHd + d4;
            cp16((unsigned)__cvta_generic_to_shared(&kd[r*QP_STR + d4]),
                 qkv + base + Dmod);
            cp16((unsigned)__cvta_generic_to_shared(&vd[r*V_STR + d4]),
                 qkv + base + 2*Dmod);
        }
        asm volatile("cp.async.commit_group;");
    };

    load_kv(0, 0);

    float m0 = -1e30f, m1 = -1e30f, l0 = 0.f, l1 = 0.f;
    float o[8][4];
#pragma unroll
    for (int nt = 0; nt < 8; nt++)
#pragma unroll
        for (int r = 0; r < 4; r++) o[nt][r] = 0.f;

    const int srcA = (lane & ~3) | (c4 >> 1);
    const int srcB = srcA + 2;
    const bool oddc = c4 & 1;

    for (int kt = 0; kt < Nseq/64; kt++) {
        const int buf = kt & 1;
        asm volatile("cp.async.wait_group 0;");
        __syncthreads();
        if (kt + 1 < Nseq/64) load_kv(kt + 1, buf ^ 1);

        float s[8][4];
#pragma unroll
        for (int nt = 0; nt < 8; nt++)
#pragma unroll
            for (int r = 0; r < 4; r++) s[nt][r] = 0.f;

#pragma unroll
        for (int k8 = 0; k8 < 8; k8++) {
            unsigned aq[4];
            LDSM_X4(aq, qs_u32 + q_off + k8*32u);
#pragma unroll
            for (int ntp = 0; ntp < 4; ntp++) {
                unsigned kb4[4];
                LDSM_X4(kb4, ks_u32[buf] + kp_off + ntp*(16u*QP_STR*4u) + k8*32u);
                MMA_TF32(s[2*ntp    ], aq[0], aq[1], aq[2], aq[3], kb4[0], kb4[1]);
                MMA_TF32(s[2*ntp + 1], aq[0], aq[1], aq[2], aq[3], kb4[2], kb4[3]);
            }
        }

        const int k0 = kt*64;
        const int qg0 = q0 + qrow + r8;
#pragma unroll
        for (int nt = 0; nt < 8; nt++) {
            int col = k0 + nt*8 + c4*2;
            float2 ad0 = *(const float2*)&adj[(size_t) qg0     *Nseq + col];
            float2 ad1 = *(const float2*)&adj[(size_t)(qg0 + 8)*Nseq + col];
            s[nt][0] = s[nt][0]*scale + ad0.x;
            s[nt][1] = s[nt][1]*scale + ad0.y;
            s[nt][2] = s[nt][2]*scale + ad1.x;
            s[nt][3] = s[nt][3]*scale + ad1.y;
        }

        float mx0 = -1e30f, mx1 = -1e30f;
#pragma unroll
        for (int nt = 0; nt < 8; nt++) {
            mx0 = fmaxf(mx0, fmaxf(s[nt][0], s[nt][1]));
            mx1 = fmaxf(mx1, fmaxf(s[nt][2], s[nt][3]));
        }
        mx0 = fmaxf(mx0, __shfl_xor_sync(0xffffffffu, mx0, 1));
        mx0 = fmaxf(mx0, __shfl_xor_sync(0xffffffffu, mx0, 2));
        mx1 = fmaxf(mx1, __shfl_xor_sync(0xffffffffu, mx1, 1));
        mx1 = fmaxf(mx1, __shfl_xor_sync(0xffffffffu, mx1, 2));
        float mn0 = fmaxf(m0, mx0), mn1 = fmaxf(m1, mx1);
        float al0 = __expf(m0 - mn0), al1 = __expf(m1 - mn1);
        float rs0 = 0.f, rs1 = 0.f;
#pragma unroll
        for (int nt = 0; nt < 8; nt++) {
            s[nt][0] = __expf(s[nt][0] - mn0);
            s[nt][1] = __expf(s[nt][1] - mn0);
            s[nt][2] = __expf(s[nt][2] - mn1);
            s[nt][3] = __expf(s[nt][3] - mn1);
            rs0 += s[nt][0] + s[nt][1];
            rs1 += s[nt][2] + s[nt][3];
        }
        rs0 += __shfl_xor_sync(0xffffffffu, rs0, 1);
        rs0 += __shfl_xor_sync(0xffffffffu, rs0, 2);
        rs1 += __shfl_xor_sync(0xffffffffu, rs1, 1);
        rs1 += __shfl_xor_sync(0xffffffffu, rs1, 2);
        l0 = l0*al0 + rs0;  l1 = l1*al1 + rs1;
        m0 = mn0;           m1 = mn1;
#pragma unroll
        for (int nt = 0; nt < 8; nt++) {
            o[nt][0] *= al0; o[nt][1] *= al0;
            o[nt][2] *= al1; o[nt][3] *= al1;
        }

        const float* vs = Vbuf[buf];
#pragma unroll
        for (int k8 = 0; k8 < 8; k8++) {
            const int kb = k8*8;
            float t0 = __shfl_sync(0xffffffffu, s[k8][0], srcA);
            float t1 = __shfl_sync(0xffffffffu, s[k8][1], srcA);
            float t2 = __shfl_sync(0xffffffffu, s[k8][2], srcA);
            float t3 = __shfl_sync(0xffffffffu, s[k8][3], srcA);
            float u0 = __shfl_sync(0xffffffffu, s[k8][0], srcB);
            float u1 = __shfl_sync(0xffffffffu, s[k8][1], srcB);
            float u2 = __shfl_sync(0xffffffffu, s[k8][2], srcB);
            float u3 = __shfl_sync(0xffffffffu, s[k8][3], srcB);
            unsigned ap0 = __float_as_uint(oddc ? t1 : t0);
            unsigned ap1 = __float_as_uint(oddc ? t3 : t2);
            unsigned ap2 = __float_as_uint(oddc ? u1 : u0);
            unsigned ap3 = __float_as_uint(oddc ? u3 : u2);
#pragma unroll
            for (int nt = 0; nt < 8; nt++) {
                unsigned b0 = __float_as_uint(vs[(kb + c4    )*V_STR + nt*8 + r8]);
                unsigned b1 = __float_as_uint(vs[(kb + c4 + 4)*V_STR + nt*8 + r8]);
                MMA_TF32(o[nt], ap0, ap1, ap2, ap3, b0, b1);
            }
        }
        __syncthreads();
    }

    const int qg0 = q0 + qrow + r8;
    float i0 = 1.f / l0, i1 = 1.f / l1;
#pragma unroll
    for (int nt = 0; nt < 8; nt++) {
        int col = h*DHd + nt*8 + c4*2;
        *(float2*)&out[(size_t)(b*Nseq + qg0    )*Dmod + col] =
            make_float2(round_tf32(o[nt][0]*i0), round_tf32(o[nt][1]*i0));
        *(float2*)&out[(size_t)(b*Nseq + qg0 + 8)*Dmod + col] =
            make_float2(round_tf32(o[nt][2]*i1), round_tf32(o[nt][3]*i1));
    }
}

// ---------------- launcher ----------------
extern "C" void kernel_launch(void* const* d_in, const int* in_sizes, int n_in,
                              void* d_out, int out_size)
{
    const float* x      = (const float*)d_in[0];
    const float* adj    = (const float*)d_in[1];
    const float* ln1_g  = (const float*)d_in[2];
    const float* ln1_b  = (const float*)d_in[3];
    const float* qkv_w  = (const float*)d_in[4];
    const float* qkv_b  = (const float*)d_in[5];
    const float* proj_w = (const float*)d_in[6];
    const float* proj_b = (const float*)d_in[7];
    const float* ln2_g  = (const float*)d_in[8];
    const float* ln2_b  = (const float*)d_in[9];
    const float* fc1_w  = (const float*)d_in[10];
    const float* fc1_b  = (const float*)d_in[11];
    const float* fc2_w  = (const float*)d_in[12];
    const float* fc2_b  = (const float*)d_in[13];
    float* out = (float*)d_out;

    float *h, *qkv, *attn, *x1, *h2, *act, *part;
    float *wqkvT, *wprojT, *wfc1T, *wfc2T;
    cudaGetSymbolAddress((void**)&h,     g_h);
    cudaGetSymbolAddress((void**)&qkv,   g_qkv);
    cudaGetSymbolAddress((void**)&attn,  g_attn);
    cudaGetSymbolAddress((void**)&x1,    g_x1);
    cudaGetSymbolAddress((void**)&h2,    g_h2);
    cudaGetSymbolAddress((void**)&act,   g_act);
    cudaGetSymbolAddress((void**)&part,  g_part);
    cudaGetSymbolAddress((void**)&wqkvT, g_wqkvT);
    cudaGetSymbolAddress((void**)&wprojT,g_wprojT);
    cudaGetSymbolAddress((void**)&wfc1T, g_wfc1T);
    cudaGetSymbolAddress((void**)&wfc2T, g_wfc2T);

    const int attn_smem = (128*QP_STR + 2*64*QP_STR + 2*64*V_STR)
                          * sizeof(float);   // 106496 B
    static cudaStream_t s2 = nullptr;
    static cudaEvent_t evA = nullptr, evQ = nullptr, evW = nullptr;
    if (!s2) {
        cudaFuncSetAttribute(gemm_tc<false,false,false,false>,
            cudaFuncAttributeMaxDynamicSharedMemorySize, GEMM_SMEM);
        cudaFuncSetAttribute(gemm_tc<true,false,false,false>,
            cudaFuncAttributeMaxDynamicSharedMemorySize, GEMM_SMEM);
        cudaFuncSetAttribute(gemm_tc<false,false,false,true>,
            cudaFuncAttributeMaxDynamicSharedMemorySize, GEMM_SMEM);
        cudaFuncSetAttribute(attn_tc,
            cudaFuncAttributeMaxDynamicSharedMemorySize, attn_smem);
        cudaStreamCreateWithFlags(&s2, cudaStreamNonBlocking);
        cudaEventCreateWithFlags(&evA, cudaEventDisableTiming);
        cudaEventCreateWithFlags(&evQ, cudaEventDisableTiming);
        cudaEventCreateWithFlags(&evW, cudaEventDisableTiming);
    }

    dim3 tb(32, 8);

    // ---- fork: side stream does all weight transposes ----
    cudaEventRecord(evA, 0);
    cudaStreamWaitEvent(s2, evA, 0);
    transpose32<<<dim3(3*Dmod/32, Dmod/32), tb, 0, s2>>>(qkv_w, wqkvT, Dmod, 3*Dmod);
    cudaEventRecord(evQ, s2);
    transpose32<<<dim3(Dmod/32, Dmod/32), tb, 0, s2>>>(proj_w, wprojT, Dmod, Dmod);
    transpose32<<<dim3(HID/32,  Dmod/32), tb, 0, s2>>>(fc1_w,  wfc1T, Dmod, HID);
    transpose32<<<dim3(Dmod/32, HID/32),  tb, 0, s2>>>(fc2_w,  wfc2T, HID, Dmod);
    cudaEventRecord(evW, s2);

    // ---- main stream: LN1 overlaps the qkv-weight transpose ----
    ln_warp<<<ROWS/8, 256>>>(x, ln1_g, ln1_b, h);
    cudaStreamWaitEvent(0, evQ, 0);
    // qkv = h @ qkv_w + qkv_b
    gemm_tc<false,false,false,false><<<dim3(18, 32, 1), 256, GEMM_SMEM>>>(
        h, wqkvT, qkv_b, nullptr, qkv, ROWS, Dmod, 3*Dmod, Dmod);
    // attention (remaining transposes hide under this)
    attn_tc<<<dim3(Nseq/128, Bsz*Hh), 256, attn_smem>>>(qkv, adj, attn);
    cudaStreamWaitEvent(0, evW, 0);
    // proj (split-K=3) then fused reduce+residual+LN2
    gemm_tc<false,false,false,true><<<dim3(6, 32, 3), 256, GEMM_SMEM>>>(
        attn, wprojT, proj_b, nullptr, part, ROWS, Dmod, Dmod, Dmod/3);
    reduce3_ln<<<ROWS/8, 256>>>(part, proj_b, x, x1, ln2_g, ln2_b, h2);
    // act = gelu(h2 @ fc1_w + fc1_b)  (no epilogue re-round; fc2 MMA truncates)
    gemm_tc<true,false,false,false><<<dim3(24, 32, 1), 256, GEMM_SMEM>>>(
        h2, wfc1T, fc1_b, nullptr, act, ROWS, Dmod, HID, Dmod);
    // out = x1 + act @ fc2_w + fc2_b  (split-K=3)
    gemm_tc<false,false,false,true><<<dim3(6, 32, 3), 256, GEMM_SMEM>>>(
        act, wfc2T, fc2_b, nullptr, part, ROWS, HID, Dmod, HID/3);
    reduce3_kernel<<<ROWS*Dmod/4/256, 256>>>(part, fc2_b, x1, out, Dmod);
}

// round 15
// speedup vs baseline: 1.1502x; 1.0265x over previous
#include <cuda_runtime.h>
#include <math.h>
#include <stdint.h>

#define Bsz  4
#define Nseq 1024
#define Dmod 768
#define Hh   12
#define DHd  64
#define HID  3072
#define ROWS (Bsz*Nseq)   // 4096
#define ROWS_H (ROWS/2)   // 2048

// ---- scratch (no cudaMalloc allowed) ----
__device__ float g_h   [ROWS*Dmod];
__device__ float g_qkv [ROWS*3*Dmod];
__device__ float g_attn[ROWS*Dmod];
__device__ float g_x1  [ROWS*Dmod];
__device__ float g_h2  [ROWS*Dmod];
__device__ float g_act [ROWS*HID];
__device__ float g_part[3*ROWS*Dmod];   // split-K partials
// transposed weights [N][K]
__device__ float g_wqkvT[3*Dmod*Dmod];
__device__ float g_wprojT[Dmod*Dmod];
__device__ float g_wfc1T[HID*Dmod];
__device__ float g_wfc2T[Dmod*HID];

__device__ __forceinline__ float round_tf32(float x) {
    unsigned r;
    asm("cvt.rna.tf32.f32 %0, %1;" : "=r"(r) : "f"(x));
    return __uint_as_float(r);
}

#define MMA_TF32(acc, a0,a1,a2,a3, b0,b1)                                   \
    asm volatile(                                                           \
        "mma.sync.aligned.m16n8k8.row.col.f32.tf32.tf32.f32 "               \
        "{%0,%1,%2,%3}, {%4,%5,%6,%7}, {%8,%9}, {%0,%1,%2,%3};"             \
        : "+f"(acc[0]), "+f"(acc[1]), "+f"(acc[2]), "+f"(acc[3])            \
        : "r"(a0), "r"(a1), "r"(a2), "r"(a3), "r"(b0), "r"(b1))

#define LDSM_X4(r, addr)                                                    \
    asm volatile("ldmatrix.sync.aligned.m8n8.x4.shared.b16 {%0,%1,%2,%3}, [%4];" \
        : "=r"((r)[0]), "=r"((r)[1]), "=r"((r)[2]), "=r"((r)[3]) : "r"(addr))

__device__ __forceinline__ void cp16(unsigned dst, const void* src) {
    asm volatile("cp.async.cg.shared.global [%0], [%1], 16;" :: "r"(dst), "l"(src));
}

// ---------------- weight transpose: [K][N] -> [N][K] ----------------
__global__ __launch_bounds__(256) void transpose32(
    const float* __restrict__ in, float* __restrict__ out, int K, int N)
{
    __shared__ float t[32][33];
    int n0 = blockIdx.x*32, k0 = blockIdx.y*32;
    int tx = threadIdx.x, ty = threadIdx.y;
#pragma unroll
    for (int i = 0; i < 4; i++)
        t[ty + i*8][tx] = in[(size_t)(k0 + ty + i*8)*N + n0 + tx];
    __syncthreads();
#pragma unroll
    for (int i = 0; i < 4; i++)
        out[(size_t)(n0 + ty + i*8)*K + k0 + tx] = t[tx][ty + i*8];
}

// ---------------- warp-per-row LayerNorm (tf32-rounded output) -------------
__global__ __launch_bounds__(256) void ln_warp(
    const float* __restrict__ x, const float* __restrict__ g,
    const float* __restrict__ b, float* __restrict__ out)
{
    const int warp = threadIdx.x >> 5, lane = threadIdx.x & 31;
    const int row  = blockIdx.x * 8 + warp;
    const float4* xr = (const float4*)(x + (size_t)row * Dmod);
    float4 v[6];
    float s = 0.f, s2 = 0.f;
#pragma unroll
    for (int i = 0; i < 6; i++) {
        v[i] = xr[lane + i*32];
        s  += v[i].x + v[i].y + v[i].z + v[i].w;
        s2 += v[i].x*v[i].x + v[i].y*v[i].y + v[i].z*v[i].z + v[i].w*v[i].w;
    }
#pragma unroll
    for (int off = 16; off; off >>= 1) {
        s  += __shfl_xor_sync(0xffffffffu, s,  off);
        s2 += __shfl_xor_sync(0xffffffffu, s2, off);
    }
    const float mu = s * (1.f/Dmod);
    const float rs = rsqrtf(s2 * (1.f/Dmod) - mu*mu + 1e-6f);
    float4* orow = (float4*)(out + (size_t)row * Dmod);
#pragma unroll
    for (int i = 0; i < 6; i++) {
        int c = lane + i*32;
        float4 gg = __ldg(&((const float4*)g)[c]);
        float4 bb = __ldg(&((const float4*)b)[c]);
        float4 o;
        o.x = round_tf32((v[i].x - mu)*rs*gg.x + bb.x);
        o.y = round_tf32((v[i].y - mu)*rs*gg.y + bb.y);
        o.z = round_tf32((v[i].z - mu)*rs*gg.z + bb.z);
        o.w = round_tf32((v[i].w - mu)*rs*gg.w + bb.w);
        orow[c] = o;
    }
}

// ------- fused split-K reduce + residual + LN: x1 and h2 in one pass -------
// Pointers pre-offset to the row-half; slab stride (tot4) spans full ROWS.
__global__ __launch_bounds__(256) void reduce3_ln(
    const float* __restrict__ p, const float* __restrict__ bias,
    const float* __restrict__ res, float* __restrict__ x1,
    const float* __restrict__ g, const float* __restrict__ bv,
    float* __restrict__ h2)
{
    const int warp = threadIdx.x >> 5, lane = threadIdx.x & 31;
    const int row  = blockIdx.x * 8 + warp;
    const size_t tot4 = (size_t)ROWS * Dmod / 4;
    const size_t base4 = (size_t)row * (Dmod/4);
    float4 v[6];
    float s = 0.f, s2 = 0.f;
#pragma unroll
    for (int i = 0; i < 6; i++) {
        int c = lane + i*32;
        size_t idx = base4 + c;
        float4 a  = ((const float4*)p)[idx];
        float4 b2 = ((const float4*)p)[idx + tot4];
        float4 c2 = ((const float4*)p)[idx + 2*tot4];
        float4 r  = ((const float4*)res)[idx];
        float4 bi = __ldg(&((const float4*)bias)[c]);
        float4 o;
        o.x = a.x + b2.x + c2.x + bi.x + r.x;
        o.y = a.y + b2.y + c2.y + bi.y + r.y;
        o.z = a.z + b2.z + c2.z + bi.z + r.z;
        o.w = a.w + b2.w + c2.w + bi.w + r.w;
        ((float4*)x1)[idx] = o;
        v[i] = o;
        s  += o.x + o.y + o.z + o.w;
        s2 += o.x*o.x + o.y*o.y + o.z*o.z + o.w*o.w;
    }
#pragma unroll
    for (int off = 16; off; off >>= 1) {
        s  += __shfl_xor_sync(0xffffffffu, s,  off);
        s2 += __shfl_xor_sync(0xffffffffu, s2, off);
    }
    const float mu = s * (1.f/Dmod);
    const float rs = rsqrtf(s2 * (1.f/Dmod) - mu*mu + 1e-6f);
#pragma unroll
    for (int i = 0; i < 6; i++) {
        int c = lane + i*32;
        float4 gg = __ldg(&((const float4*)g)[c]);
        float4 bb = __ldg(&((const float4*)bv)[c]);
        float4 o;
        o.x = round_tf32((v[i].x - mu)*rs*gg.x + bb.x);
        o.y = round_tf32((v[i].y - mu)*rs*gg.y + bb.y);
        o.z = round_tf32((v[i].z - mu)*rs*gg.z + bb.z);
        o.w = round_tf32((v[i].w - mu)*rs*gg.w + bb.w);
        ((float4*)h2)[base4 + c] = o;
    }
}

// ---------------- split-K reduction: out = p0+p1+p2 + bias + res ----------
__global__ __launch_bounds__(256) void reduce3_kernel(
    const float* __restrict__ p, const float* __restrict__ bias,
    const float* __restrict__ res, float* __restrict__ out, int Nc)
{
    int i = blockIdx.x * 256 + threadIdx.x;
    const size_t tot = (size_t)ROWS * Nc;
    float4 a = ((const float4*)p)[i];
    float4 b = ((const float4*)(p + tot))[i];
    float4 c = ((const float4*)(p + 2*tot))[i];
    float4 r = ((const float4*)res)[i];
    int col = (i*4) % Nc;
    const float4 bi = *(const float4*)&bias[col];
    float4 o;
    o.x = a.x + b.x + c.x + bi.x + r.x;
    o.y = a.y + b.y + c.y + bi.y + r.y;
    o.z = a.z + b.z + c.z + bi.z + r.z;
    o.w = a.w + b.w + c.w + bi.w + r.w;
    ((float4*)out)[i] = o;
}

// --------- tf32 GEMM 128x128, 3-stage, full-LDSM (W pre-transposed) --------
#define TS 36
#define STAGE_FLOATS (2*128*TS)
#define GEMM_SMEM (3*STAGE_FLOATS*4)

template<bool GELU, bool RES, bool ROUND, bool PARTIAL>
__global__ __launch_bounds__(256, 2) void gemm_tc(
    const float* __restrict__ A, const float* __restrict__ WT,
    const float* __restrict__ bias, const float* __restrict__ res,
    float* __restrict__ C, int M, int Kfull, int Nc, int Ks)
{
    extern __shared__ float sm[];

    const int tid  = threadIdx.x;
    const int lane = tid & 31;
    const int warp = tid >> 5;
    const int wm   = warp & 1;
    const int wn   = warp >> 1;
    const int bm   = blockIdx.y * 128;
    const int bn   = blockIdx.x * 128;
    const int z    = blockIdx.z;

    const float* Ab = A  + (size_t)z * Ks;
    const float* Wb = WT + (size_t)z * Ks;
    float* Cb = PARTIAL ? (C + (size_t)z * M * Nc) : C;

    float acc[4][4][4];
#pragma unroll
    for (int i = 0; i < 4; i++)
#pragma unroll
        for (int j = 0; j < 4; j++)
#pragma unroll
            for (int r = 0; r < 4; r++) acc[i][j][r] = 0.f;

    const int kTiles = Ks >> 5;

    auto load_stage = [&](int kt, int buf) {
        const int k0 = kt * 32;
        float* As = sm + buf*STAGE_FLOATS;
        float* Bs = As + 128*TS;
#pragma unroll
        for (int i = 0; i < 4; i++) {
            int idx = tid + i*256;
            int r = idx >> 3, kk = (idx & 7) * 4;
            cp16((unsigned)__cvta_generic_to_shared(&As[r*TS + kk]),
                 Ab + (size_t)(bm + r) * Kfull + k0 + kk);
        }
#pragma unroll
        for (int i = 0; i < 4; i++) {
            int idx = tid + i*256;
            int r = idx >> 3, kk = (idx & 7) * 4;
            cp16((unsigned)__cvta_generic_to_shared(&Bs[r*TS + kk]),
                 Wb + (size_t)(bn + r) * Kfull + k0 + kk);
        }
        asm volatile("cp.async.commit_group;");
    };

    load_stage(0, 0);
    load_stage(1, 1);

    const int r8 = lane >> 2;
    const int c4 = lane & 3;
    const int lrow = ((lane >> 3) & 1) * 8 + (lane & 7);
    const int lcol = (lane >> 4) * 4;
    const int kprow = ((lane >> 4) & 1) * 8 + (lane & 7);
    const int kpcol = ((lane >> 3) & 1) * 4;

    const uint32_t a_base = ((wm*64 + lrow)*TS + lcol) * 4u;
    const uint32_t b_base = ((wn*32 + kprow)*TS + kpcol) * 4u;

    for (int kt = 0; kt < kTiles; kt++) {
        if (kt + 1 < kTiles) asm volatile("cp.async.wait_group 1;");
        else                 asm volatile("cp.async.wait_group 0;");
        __syncthreads();
        if (kt + 2 < kTiles) load_stage(kt + 2, (kt + 2) % 3);

        const int buf = kt % 3;
        const uint32_t as_u32 = (uint32_t)__cvta_generic_to_shared(sm)
                                + buf*STAGE_FLOATS*4u;
        const uint32_t bs_u32 = as_u32 + 128*TS*4u;
#pragma unroll
        for (int k8 = 0; k8 < 4; k8++) {
            unsigned af[4][4], bf[2][4];
#pragma unroll
            for (int mt = 0; mt < 4; mt++)
                LDSM_X4(af[mt], as_u32 + a_base + mt*(16u*TS*4u) + k8*32u);
#pragma unroll
            for (int p = 0; p < 2; p++)
                LDSM_X4(bf[p], bs_u32 + b_base + p*(16u*TS*4u) + k8*32u);
#pragma unroll
            for (int mt = 0; mt < 4; mt++) {
                MMA_TF32(acc[mt][0], af[mt][0], af[mt][1], af[mt][2], af[mt][3],
                         bf[0][0], bf[0][1]);
                MMA_TF32(acc[mt][1], af[mt][0], af[mt][1], af[mt][2], af[mt][3],
                         bf[0][2], bf[0][3]);
                MMA_TF32(acc[mt][2], af[mt][0], af[mt][1], af[mt][2], af[mt][3],
                         bf[1][0], bf[1][1]);
                MMA_TF32(acc[mt][3], af[mt][0], af[mt][1], af[mt][2], af[mt][3],
                         bf[1][2], bf[1][3]);
            }
        }
    }

#pragma unroll
    for (int mt = 0; mt < 4; mt++) {
        int row0 = bm + wm*64 + mt*16 + r8;
#pragma unroll
        for (int nt = 0; nt < 4; nt++) {
            int col0 = bn + wn*32 + nt*8 + c4*2;
            float b0 = 0.f, b1 = 0.f;
            if (!PARTIAL) { b0 = __ldg(&bias[col0]); b1 = __ldg(&bias[col0 + 1]); }
#pragma unroll
            for (int half = 0; half < 2; half++) {
                int row = row0 + half*8;
                float v0 = acc[mt][nt][half*2 + 0] + b0;
                float v1 = acc[mt][nt][half*2 + 1] + b1;
                if (GELU) { v0 = v0 * normcdff(v0); v1 = v1 * normcdff(v1); }
                if (RES) {
                    const float2 rr = *(const float2*)&res[(size_t)row*Nc + col0];
                    v0 += rr.x; v1 += rr.y;
                }
                if (ROUND) { v0 = round_tf32(v0); v1 = round_tf32(v1); }
                *(float2*)&Cb[(size_t)row*Nc + col0] = make_float2(v0, v1);
            }
        }
    }
}

// ------- Tensor-core flash attention: cp.async double-buffer, no P smem ----
#define QP_STR 68
#define V_STR  72

__global__ __launch_bounds__(256) void attn_tc(
    const float* __restrict__ qkv, const float* __restrict__ adj,
    float* __restrict__ out, int bh0)
{
    extern __shared__ float sma[];
    float* Qs  = sma;
    float* Kb0 = Qs + 128*QP_STR;
    float* Vb0 = Kb0 + 2*64*QP_STR;

    const int tid  = threadIdx.x;
    const int lane = tid & 31;
    const int warp = tid >> 5;
    const int r8   = lane >> 2;
    const int c4   = lane & 3;
    const int bh   = blockIdx.y + bh0;
    const int b    = bh / Hh, h = bh % Hh;
    const int q0   = blockIdx.x * 128;
    const int qrow = (warp >> 2)*64 + (warp & 3)*16;
    const float scale = 0.125f;

    const int lrow  = ((lane >> 3) & 1) * 8 + (lane & 7);
    const int lcol  = (lane >> 4) * 4;
    const int kprow = ((lane >> 4) & 1) * 8 + (lane & 7);
    const int kpcol = ((lane >> 3) & 1) * 4;

    const uint32_t qs_u32 = (uint32_t)__cvta_generic_to_shared(Qs);
    uint32_t ks_u32[2] = {
        (uint32_t)__cvta_generic_to_shared(Kb0),
        (uint32_t)__cvta_generic_to_shared(Kb0 + 64*QP_STR) };
    float* Vbuf[2] = { Vb0, Vb0 + 64*V_STR };
    const uint32_t q_off  = ((qrow + lrow)*QP_STR + lcol) * 4u;
    const uint32_t kp_off = (kprow*QP_STR + kpcol) * 4u;

#pragma unroll
    for (int it = 0; it < 8; it++) {
        int idx = tid + it*256;
        int r = idx >> 4, d4 = (idx & 15) * 4;
        float4 q4 = *(const float4*)&qkv[(size_t)(b*Nseq + q0 + r)*(3*Dmod)
                                         + h*DHd + d4];
        *(float4*)&Qs[r*QP_STR + d4] = q4;
    }

    auto load_kv = [&](int kt, int buf) {
        const int k0 = kt*64;
        float* kd = Kb0 + buf*64*QP_STR;
        float* vd = Vbuf[buf];
#pragma unroll
        for (int i = 0; i < 4; i++) {
            int idx = tid + i*256;
            int r = idx >> 4, d4 = (idx & 15) * 4;
            size_t base = (size_t)(b*Nseq + k0 + r)*(3*Dmod) + h*DHd + d4;
            cp16((unsigned)__cvta_generic_to_shared(&kd[r*QP_STR + d4]),
                 qkv + base + Dmod);
            cp16((unsigned)__cvta_generic_to_shared(&vd[r*V_STR + d4]),
                 qkv + base + 2*Dmod);
        }
        asm volatile("cp.async.commit_group;");
    };

    load_kv(0, 0);

    float m0 = -1e30f, m1 = -1e30f, l0 = 0.f, l1 = 0.f;
    float o[8][4];
#pragma unroll
    for (int nt = 0; nt < 8; nt++)
#pragma unroll
        for (int r = 0; r < 4; r++) o[nt][r] = 0.f;

    const int srcA = (lane & ~3) | (c4 >> 1);
    const int srcB = srcA + 2;
    const bool oddc = c4 & 1;

    for (int kt = 0; kt < Nseq/64; kt++) {
        const int buf = kt & 1;
        asm volatile("cp.async.wait_group 0;");
        __syncthreads();
        if (kt + 1 < Nseq/64) load_kv(kt + 1, buf ^ 1);

        float s[8][4];
#pragma unroll
        for (int nt = 0; nt < 8; nt++)
#pragma unroll
            for (int r = 0; r < 4; r++) s[nt][r] = 0.f;

#pragma unroll
        for (int k8 = 0; k8 < 8; k8++) {
            unsigned aq[4];
            LDSM_X4(aq, qs_u32 + q_off + k8*32u);
#pragma unroll
            for (int ntp = 0; ntp < 4; ntp++) {
                unsigned kb4[4];
                LDSM_X4(kb4, ks_u32[buf] + kp_off + ntp*(16u*QP_STR*4u) + k8*32u);
                MMA_TF32(s[2*ntp    ], aq[0], aq[1], aq[2], aq[3], kb4[0], kb4[1]);
                MMA_TF32(s[2*ntp + 1], aq[0], aq[1], aq[2], aq[3], kb4[2], kb4[3]);
            }
        }

        const int k0 = kt*64;
        const int qg0 = q0 + qrow + r8;
#pragma unroll
        for (int nt = 0; nt < 8; nt++) {
            int col = k0 + nt*8 + c4*2;
            float2 ad0 = *(const float2*)&adj[(size_t) qg0     *Nseq + col];
            float2 ad1 = *(const float2*)&adj[(size_t)(qg0 + 8)*Nseq + col];
            s[nt][0] = s[nt][0]*scale + ad0.x;
            s[nt][1] = s[nt][1]*scale + ad0.y;
            s[nt][2] = s[nt][2]*scale + ad1.x;
            s[nt][3] = s[nt][3]*scale + ad1.y;
        }

        float mx0 = -1e30f, mx1 = -1e30f;
#pragma unroll
        for (int nt = 0; nt < 8; nt++) {
            mx0 = fmaxf(mx0, fmaxf(s[nt][0], s[nt][1]));
            mx1 = fmaxf(mx1, fmaxf(s[nt][2], s[nt][3]));
        }
        mx0 = fmaxf(mx0, __shfl_xor_sync(0xffffffffu, mx0, 1));
        mx0 = fmaxf(mx0, __shfl_xor_sync(0xffffffffu, mx0, 2));
        mx1 = fmaxf(mx1, __shfl_xor_sync(0xffffffffu, mx1, 1));
        mx1 = fmaxf(mx1, __shfl_xor_sync(0xffffffffu, mx1, 2));
        float mn0 = fmaxf(m0, mx0), mn1 = fmaxf(m1, mx1);
        float al0 = __expf(m0 - mn0), al1 = __expf(m1 - mn1);
        float rs0 = 0.f, rs1 = 0.f;
#pragma unroll
        for (int nt = 0; nt < 8; nt++) {
            s[nt][0] = __expf(s[nt][0] - mn0);
            s[nt][1] = __expf(s[nt][1] - mn0);
            s[nt][2] = __expf(s[nt][2] - mn1);
            s[nt][3] = __expf(s[nt][3] - mn1);
            rs0 += s[nt][0] + s[nt][1];
            rs1 += s[nt][2] + s[nt][3];
        }
        rs0 += __shfl_xor_sync(0xffffffffu, rs0, 1);
        rs0 += __shfl_xor_sync(0xffffffffu, rs0, 2);
        rs1 += __shfl_xor_sync(0xffffffffu, rs1, 1);
        rs1 += __shfl_xor_sync(0xffffffffu, rs1, 2);
        l0 = l0*al0 + rs0;  l1 = l1*al1 + rs1;
        m0 = mn0;           m1 = mn1;
#pragma unroll
        for (int nt = 0; nt < 8; nt++) {
            o[nt][0] *= al0; o[nt][1] *= al0;
            o[nt][2] *= al1; o[nt][3] *= al1;
        }

        const float* vs = Vbuf[buf];
#pragma unroll
        for (int k8 = 0; k8 < 8; k8++) {
            const int kb = k8*8;
            float t0 = __shfl_sync(0xffffffffu, s[k8][0], srcA);
            float t1 = __shfl_sync(0xffffffffu, s[k8][1], srcA);
            float t2 = __shfl_sync(0xffffffffu, s[k8][2], srcA);
            float t3 = __shfl_sync(0xffffffffu, s[k8][3], srcA);
            float u0 = __shfl_sync(0xffffffffu, s[k8][0], srcB);
            float u1 = __shfl_sync(0xffffffffu, s[k8][1], srcB);
            float u2 = __shfl_sync(0xffffffffu, s[k8][2], srcB);
            float u3 = __shfl_sync(0xffffffffu, s[k8][3], srcB);
            unsigned ap0 = __float_as_uint(oddc ? t1 : t0);
            unsigned ap1 = __float_as_uint(oddc ? t3 : t2);
            unsigned ap2 = __float_as_uint(oddc ? u1 : u0);
            unsigned ap3 = __float_as_uint(oddc ? u3 : u2);
#pragma unroll
            for (int nt = 0; nt < 8; nt++) {
                unsigned b0 = __float_as_uint(vs[(kb + c4    )*V_STR + nt*8 + r8]);
                unsigned b1 = __float_as_uint(vs[(kb + c4 + 4)*V_STR + nt*8 + r8]);
                MMA_TF32(o[nt], ap0, ap1, ap2, ap3, b0, b1);
            }
        }
        __syncthreads();
    }

    const int qg0 = q0 + qrow + r8;
    float i0 = 1.f / l0, i1 = 1.f / l1;
#pragma unroll
    for (int nt = 0; nt < 8; nt++) {
        int col = h*DHd + nt*8 + c4*2;
        *(float2*)&out[(size_t)(b*Nseq + qg0    )*Dmod + col] =
            make_float2(round_tf32(o[nt][0]*i0), round_tf32(o[nt][1]*i0));
        *(float2*)&out[(size_t)(b*Nseq + qg0 + 8)*Dmod + col] =
            make_float2(round_tf32(o[nt][2]*i1), round_tf32(o[nt][3]*i1));
    }
}

// ---------------- launcher: two-half pipelined DAG ----------------
extern "C" void kernel_launch(void* const* d_in, const int* in_sizes, int n_in,
                              void* d_out, int out_size)
{
    const float* x      = (const float*)d_in[0];
    const float* adj    = (const float*)d_in[1];
    const float* ln1_g  = (const float*)d_in[2];
    const float* ln1_b  = (const float*)d_in[3];
    const float* qkv_w  = (const float*)d_in[4];
    const float* qkv_b  = (const float*)d_in[5];
    const float* proj_w = (const float*)d_in[6];
    const float* proj_b = (const float*)d_in[7];
    const float* ln2_g  = (const float*)d_in[8];
    const float* ln2_b  = (const float*)d_in[9];
    const float* fc1_w  = (const float*)d_in[10];
    const float* fc1_b  = (const float*)d_in[11];
    const float* fc2_w  = (const float*)d_in[12];
    const float* fc2_b  = (const float*)d_in[13];
    float* out = (float*)d_out;

    float *h, *qkv, *attn, *x1, *h2, *act, *part;
    float *wqkvT, *wprojT, *wfc1T, *wfc2T;
    cudaGetSymbolAddress((void**)&h,     g_h);
    cudaGetSymbolAddress((void**)&qkv,   g_qkv);
    cudaGetSymbolAddress((void**)&attn,  g_attn);
    cudaGetSymbolAddress((void**)&x1,    g_x1);
    cudaGetSymbolAddress((void**)&h2,    g_h2);
    cudaGetSymbolAddress((void**)&act,   g_act);
    cudaGetSymbolAddress((void**)&part,  g_part);
    cudaGetSymbolAddress((void**)&wqkvT, g_wqkvT);
    cudaGetSymbolAddress((void**)&wprojT,g_wprojT);
    cudaGetSymbolAddress((void**)&wfc1T, g_wfc1T);
    cudaGetSymbolAddress((void**)&wfc2T, g_wfc2T);

    const int attn_smem = (128*QP_STR + 2*64*QP_STR + 2*64*V_STR)
                          * sizeof(float);   // 106496 B
    static cudaStream_t s2 = nullptr;
    static cudaEvent_t evA = nullptr, evQ = nullptr, evW = nullptr;
    static cudaEvent_t eK0 = nullptr, eK1 = nullptr, eA0 = nullptr,
                       eEnd = nullptr;
    if (!s2) {
        cudaFuncSetAttribute(gemm_tc<false,false,false,false>,
            cudaFuncAttributeMaxDynamicSharedMemorySize, GEMM_SMEM);
        cudaFuncSetAttribute(gemm_tc<true,false,false,false>,
            cudaFuncAttributeMaxDynamicSharedMemorySize, GEMM_SMEM);
        cudaFuncSetAttribute(gemm_tc<false,false,false,true>,
            cudaFuncAttributeMaxDynamicSharedMemorySize, GEMM_SMEM);
        cudaFuncSetAttribute(attn_tc,
            cudaFuncAttributeMaxDynamicSharedMemorySize, attn_smem);
        cudaStreamCreateWithFlags(&s2, cudaStreamNonBlocking);
        cudaEventCreateWithFlags(&evA, cudaEventDisableTiming);
        cudaEventCreateWithFlags(&evQ, cudaEventDisableTiming);
        cudaEventCreateWithFlags(&evW, cudaEventDisableTiming);
        cudaEventCreateWithFlags(&eK0, cudaEventDisableTiming);
        cudaEventCreateWithFlags(&eK1, cudaEventDisableTiming);
        cudaEventCreateWithFlags(&eA0, cudaEventDisableTiming);
        cudaEventCreateWithFlags(&eEnd, cudaEventDisableTiming);
    }

    dim3 tb(32, 8);
    const size_t off1 = (size_t)ROWS_H;   // row offset of half 1

    // ---- fork: s2 does the weight transposes ----
    cudaEventRecord(evA, 0);
    cudaStreamWaitEvent(s2, evA, 0);
    transpose32<<<dim3(3*Dmod/32, Dmod/32), tb, 0, s2>>>(qkv_w, wqkvT, Dmod, 3*Dmod);
    cudaEventRecord(evQ, s2);
    transpose32<<<dim3(Dmod/32, Dmod/32), tb, 0, s2>>>(proj_w, wprojT, Dmod, Dmod);
    transpose32<<<dim3(HID/32,  Dmod/32), tb, 0, s2>>>(fc1_w,  wfc1T, Dmod, HID);
    transpose32<<<dim3(Dmod/32, HID/32),  tb, 0, s2>>>(fc2_w,  wfc2T, HID, Dmod);
    cudaEventRecord(evW, s2);

    // ---- main stream: LN1 (all rows) overlaps qkv-weight transpose ----
    ln_warp<<<ROWS/8, 256>>>(x, ln1_g, ln1_b, h);
    cudaStreamWaitEvent(0, evQ, 0);
    // qkv halves
    gemm_tc<false,false,false,false><<<dim3(18, 16, 1), 256, GEMM_SMEM>>>(
        h, wqkvT, qkv_b, nullptr, qkv, ROWS, Dmod, 3*Dmod, Dmod);
    cudaEventRecord(eK0, 0);
    gemm_tc<false,false,false,false><<<dim3(18, 16, 1), 256, GEMM_SMEM>>>(
        h + off1*Dmod, wqkvT, qkv_b, nullptr, qkv + off1*3*Dmod,
        ROWS, Dmod, 3*Dmod, Dmod);
    cudaEventRecord(eK1, 0);

    // ---- s2: attention halves (after its transposes) ----
    cudaStreamWaitEvent(s2, eK0, 0);
    attn_tc<<<dim3(Nseq/128, Bsz*Hh/2), 256, attn_smem, s2>>>(qkv, adj, attn, 0);
    cudaEventRecord(eA0, s2);
    cudaStreamWaitEvent(s2, eK1, 0);
    attn_tc<<<dim3(Nseq/128, Bsz*Hh/2), 256, attn_smem, s2>>>(qkv, adj, attn,
                                                              Bsz*Hh/2);

    // ---- stream 0: MLP chain for half 0 (waits attn half 0 + weights) ----
    cudaStreamWaitEvent(0, eA0, 0);
    cudaStreamWaitEvent(0, evW, 0);
    gemm_tc<false,false,false,true><<<dim3(6, 16, 3), 256, GEMM_SMEM>>>(
        attn, wprojT, proj_b, nullptr, part, ROWS, Dmod, Dmod, Dmod/3);
    reduce3_ln<<<ROWS_H/8, 256>>>(part, proj_b, x, x1, ln2_g, ln2_b, h2);
    gemm_tc<true,false,false,false><<<dim3(24, 16, 1), 256, GEMM_SMEM>>>(
        h2, wfc1T, fc1_b, nullptr, act, ROWS, Dmod, HID, Dmod);
    gemm_tc<false,false,false,true><<<dim3(6, 16, 3), 256, GEMM_SMEM>>>(
        act, wfc2T, fc2_b, nullptr, part, ROWS, HID, Dmod, HID/3);
    reduce3_kernel<<<ROWS_H*Dmod/4/256, 256>>>(part, fc2_b, x1, out, Dmod);

    // ---- s2: MLP chain for half 1 (runs after attn half 1, concurrent) ----
    gemm_tc<false,false,false,true><<<dim3(6, 16, 3), 256, GEMM_SMEM, s2>>>(
        attn + off1*Dmod, wprojT, proj_b, nullptr, part + off1*Dmod,
        ROWS, Dmod, Dmod, Dmod/3);
    reduce3_ln<<<ROWS_H/8, 256, 0, s2>>>(
        part + off1*Dmod, proj_b, x + off1*Dmod, x1 + off1*Dmod,
        ln2_g, ln2_b, h2 + off1*Dmod);
    gemm_tc<true,false,false,false><<<dim3(24, 16, 1), 256, GEMM_SMEM, s2>>>(
        h2 + off1*Dmod, wfc1T, fc1_b, nullptr, act + off1*HID,
        ROWS, Dmod, HID, Dmod);
    gemm_tc<false,false,false,true><<<dim3(6, 16, 3), 256, GEMM_SMEM, s2>>>(
        act + off1*HID, wfc2T, fc2_b, nullptr, part + off1*Dmod,
        ROWS, HID, Dmod, HID/3);
    reduce3_kernel<<<ROWS_H*Dmod/4/256, 256, 0, s2>>>(
        part + off1*Dmod, fc2_b, x1 + off1*Dmod, out + off1*Dmod, Dmod);
    cudaEventRecord(eEnd, s2);

    // ---- join ----
    cudaStreamWaitEvent(0, eEnd, 0);
}

// round 16
// speedup vs baseline: 1.8838x; 1.6378x over previous
#include <cuda_runtime.h>
#include <cuda_fp16.h>
#include <math.h>
#include <stdint.h>

#define Bsz  4
#define Nseq 1024
#define Dmod 768
#define Hh   12
#define DHd  64
#define HID  3072
#define ROWS (Bsz*Nseq)   // 4096
#define ROWS_H (ROWS/2)   // 2048

// ---- scratch (no cudaMalloc allowed) ----
__device__ __half g_h   [ROWS*Dmod];
__device__ __half g_qkv [ROWS*3*Dmod];
__device__ __half g_attn[ROWS*Dmod];
__device__ float  g_x1  [ROWS*Dmod];
__device__ __half g_h2  [ROWS*Dmod];
__device__ __half g_act [ROWS*HID];
__device__ float  g_part[3*ROWS*Dmod];   // split-K partials (fp32)
// transposed weights [N][K], fp16
__device__ __half g_wqkvT[3*Dmod*Dmod];
__device__ __half g_wprojT[Dmod*Dmod];
__device__ __half g_wfc1T[HID*Dmod];
__device__ __half g_wfc2T[Dmod*HID];

__device__ __forceinline__ unsigned packh2(float lo, float hi) {
    unsigned r;
    asm("cvt.rn.f16x2.f32 %0, %1, %2;" : "=r"(r) : "f"(hi), "f"(lo));
    return r;
}

#define MMA_F16(acc, a0,a1,a2,a3, b0,b1)                                    \
    asm volatile(                                                           \
        "mma.sync.aligned.m16n8k16.row.col.f32.f16.f16.f32 "                \
        "{%0,%1,%2,%3}, {%4,%5,%6,%7}, {%8,%9}, {%0,%1,%2,%3};"             \
        : "+f"(acc[0]), "+f"(acc[1]), "+f"(acc[2]), "+f"(acc[3])            \
        : "r"(a0), "r"(a1), "r"(a2), "r"(a3), "r"(b0), "r"(b1))

#define LDSM_X4(r, addr)                                                    \
    asm volatile("ldmatrix.sync.aligned.m8n8.x4.shared.b16 {%0,%1,%2,%3}, [%4];" \
        : "=r"((r)[0]), "=r"((r)[1]), "=r"((r)[2]), "=r"((r)[3]) : "r"(addr))

#define LDSM_X4T(r, addr)                                                   \
    asm volatile("ldmatrix.sync.aligned.m8n8.x4.trans.shared.b16 {%0,%1,%2,%3}, [%4];" \
        : "=r"((r)[0]), "=r"((r)[1]), "=r"((r)[2]), "=r"((r)[3]) : "r"(addr))

__device__ __forceinline__ void cp16(unsigned dst, const void* src) {
    asm volatile("cp.async.cg.shared.global [%0], [%1], 16;" :: "r"(dst), "l"(src));
}

// ---------------- weight transpose: [K][N] fp32 -> [N][K] fp16 -------------
__global__ __launch_bounds__(256) void transpose32(
    const float* __restrict__ in, __half* __restrict__ out, int K, int N)
{
    __shared__ float t[32][33];
    int n0 = blockIdx.x*32, k0 = blockIdx.y*32;
    int tx = threadIdx.x, ty = threadIdx.y;
#pragma unroll
    for (int i = 0; i < 4; i++)
        t[ty + i*8][tx] = in[(size_t)(k0 + ty + i*8)*N + n0 + tx];
    __syncthreads();
#pragma unroll
    for (int i = 0; i < 4; i++)
        out[(size_t)(n0 + ty + i*8)*K + k0 + tx] = __float2half_rn(t[tx][ty + i*8]);
}

// ---------------- warp-per-row LayerNorm (fp16 output) ---------------------
__global__ __launch_bounds__(256) void ln_warp(
    const float* __restrict__ x, const float* __restrict__ g,
    const float* __restrict__ b, __half* __restrict__ out)
{
    const int warp = threadIdx.x >> 5, lane = threadIdx.x & 31;
    const int row  = blockIdx.x * 8 + warp;
    const float4* xr = (const float4*)(x + (size_t)row * Dmod);
    float4 v[6];
    float s = 0.f, s2 = 0.f;
#pragma unroll
    for (int i = 0; i < 6; i++) {
        v[i] = xr[lane + i*32];
        s  += v[i].x + v[i].y + v[i].z + v[i].w;
        s2 += v[i].x*v[i].x + v[i].y*v[i].y + v[i].z*v[i].z + v[i].w*v[i].w;
    }
#pragma unroll
    for (int off = 16; off; off >>= 1) {
        s  += __shfl_xor_sync(0xffffffffu, s,  off);
        s2 += __shfl_xor_sync(0xffffffffu, s2, off);
    }
    const float mu = s * (1.f/Dmod);
    const float rs = rsqrtf(s2 * (1.f/Dmod) - mu*mu + 1e-6f);
    uint2* orow = (uint2*)(out + (size_t)row * Dmod);
#pragma unroll
    for (int i = 0; i < 6; i++) {
        int c = lane + i*32;
        float4 gg = __ldg(&((const float4*)g)[c]);
        float4 bb = __ldg(&((const float4*)b)[c]);
        uint2 u;
        u.x = packh2((v[i].x - mu)*rs*gg.x + bb.x, (v[i].y - mu)*rs*gg.y + bb.y);
        u.y = packh2((v[i].z - mu)*rs*gg.z + bb.z, (v[i].w - mu)*rs*gg.w + bb.w);
        orow[c] = u;
    }
}

// ------- fused split-K reduce + residual + LN: x1(f32) and h2(f16) --------
__global__ __launch_bounds__(256) void reduce3_ln(
    const float* __restrict__ p, const float* __restrict__ bias,
    const float* __restrict__ res, float* __restrict__ x1,
    const float* __restrict__ g, const float* __restrict__ bv,
    __half* __restrict__ h2)
{
    const int warp = threadIdx.x >> 5, lane = threadIdx.x & 31;
    const int row  = blockIdx.x * 8 + warp;
    const size_t tot4 = (size_t)ROWS * Dmod / 4;
    const size_t base4 = (size_t)row * (Dmod/4);
    float4 v[6];
    float s = 0.f, s2 = 0.f;
#pragma unroll
    for (int i = 0; i < 6; i++) {
        int c = lane + i*32;
        size_t idx = base4 + c;
        float4 a  = ((const float4*)p)[idx];
        float4 b2 = ((const float4*)p)[idx + tot4];
        float4 c2 = ((const float4*)p)[idx + 2*tot4];
        float4 r  = ((const float4*)res)[idx];
        float4 bi = __ldg(&((const float4*)bias)[c]);
        float4 o;
        o.x = a.x + b2.x + c2.x + bi.x + r.x;
        o.y = a.y + b2.y + c2.y + bi.y + r.y;
        o.z = a.z + b2.z + c2.z + bi.z + r.z;
        o.w = a.w + b2.w + c2.w + bi.w + r.w;
        ((float4*)x1)[idx] = o;
        v[i] = o;
        s  += o.x + o.y + o.z + o.w;
        s2 += o.x*o.x + o.y*o.y + o.z*o.z + o.w*o.w;
    }
#pragma unroll
    for (int off = 16; off; off >>= 1) {
        s  += __shfl_xor_sync(0xffffffffu, s,  off);
        s2 += __shfl_xor_sync(0xffffffffu, s2, off);
    }
    const float mu = s * (1.f/Dmod);
    const float rs = rsqrtf(s2 * (1.f/Dmod) - mu*mu + 1e-6f);
    uint2* hrow = (uint2*)(h2 + (size_t)row * Dmod);
#pragma unroll
    for (int i = 0; i < 6; i++) {
        int c = lane + i*32;
        float4 gg = __ldg(&((const float4*)g)[c]);
        float4 bb = __ldg(&((const float4*)bv)[c]);
        uint2 u;
        u.x = packh2((v[i].x - mu)*rs*gg.x + bb.x, (v[i].y - mu)*rs*gg.y + bb.y);
        u.y = packh2((v[i].z - mu)*rs*gg.z + bb.z, (v[i].w - mu)*rs*gg.w + bb.w);
        hrow[c] = u;
    }
}

// ---------------- split-K reduction: out = p0+p1+p2 + bias + res (f32) ----
__global__ __launch_bounds__(256) void reduce3_kernel(
    const float* __restrict__ p, const float* __restrict__ bias,
    const float* __restrict__ res, float* __restrict__ out, int Nc)
{
    int i = blockIdx.x * 256 + threadIdx.x;
    const size_t tot = (size_t)ROWS * Nc;
    float4 a = ((const float4*)p)[i];
    float4 b = ((const float4*)(p + tot))[i];
    float4 c = ((const float4*)(p + 2*tot))[i];
    float4 r = ((const float4*)res)[i];
    int col = (i*4) % Nc;
    const float4 bi = *(const float4*)&bias[col];
    float4 o;
    o.x = a.x + b.x + c.x + bi.x + r.x;
    o.y = a.y + b.y + c.y + bi.y + r.y;
    o.z = a.z + b.z + c.z + bi.z + r.z;
    o.w = a.w + b.w + c.w + bi.w + r.w;
    ((float4*)out)[i] = o;
}

// --------- fp16 GEMM 128x128, K-tile 64, 3-stage, full-LDSM ---------------
#define TSH 72                          // half stride (144 B, conflict-free)
#define STAGE_H (2*128*TSH)             // halves per stage
#define GEMM_SMEM (3*STAGE_H*2)         // 110592 B

template<bool GELU, bool PARTIAL, bool HOUT>
__global__ __launch_bounds__(256, 2) void gemm_tc(
    const __half* __restrict__ A, const __half* __restrict__ WT,
    const float* __restrict__ bias, void* __restrict__ Cv,
    int M, int Kfull, int Nc, int Ks)
{
    extern __shared__ __half smh[];

    const int tid  = threadIdx.x;
    const int lane = tid & 31;
    const int warp = tid >> 5;
    const int wm   = warp & 1;
    const int wn   = warp >> 1;
    const int bm   = blockIdx.y * 128;
    const int bn   = blockIdx.x * 128;
    const int z    = blockIdx.z;

    const __half* Ab = A  + (size_t)z * Ks;
    const __half* Wb = WT + (size_t)z * Ks;

    float acc[4][4][4];
#pragma unroll
    for (int i = 0; i < 4; i++)
#pragma unroll
        for (int j = 0; j < 4; j++)
#pragma unroll
            for (int r = 0; r < 4; r++) acc[i][j][r] = 0.f;

    const int kTiles = Ks >> 6;   // K-tile = 64

    auto load_stage = [&](int kt, int buf) {
        const int k0 = kt * 64;
        __half* As = smh + buf*STAGE_H;
        __half* Bs = As + 128*TSH;
#pragma unroll
        for (int i = 0; i < 4; i++) {     // A: 128 rows x 64 halves
            int idx = tid + i*256;
            int r = idx >> 3, kc = (idx & 7) * 8;
            cp16((unsigned)__cvta_generic_to_shared(&As[r*TSH + kc]),
                 Ab + (size_t)(bm + r) * Kfull + k0 + kc);
        }
#pragma unroll
        for (int i = 0; i < 4; i++) {     // B: 128 rows x 64 halves
            int idx = tid + i*256;
            int r = idx >> 3, kc = (idx & 7) * 8;
            cp16((unsigned)__cvta_generic_to_shared(&Bs[r*TSH + kc]),
                 Wb + (size_t)(bn + r) * Kfull + k0 + kc);
        }
        asm volatile("cp.async.commit_group;");
    };

    load_stage(0, 0);
    load_stage(1, 1);

    const int r8 = lane >> 2;
    const int c4 = lane & 3;
    // A fragment (m16k16) lane address
    const int lrow = ((lane >> 3) & 1) * 8 + (lane & 7);
    const int acol = (lane >> 4) * 8;            // halves
    // B pair fragment (n16k16) lane address
    const int bprow = ((lane >> 4) & 1) * 8 + (lane & 7);
    const int bpcol = ((lane >> 3) & 1) * 8;     // halves

    const uint32_t a_base = ((wm*64 + lrow)*TSH + acol) * 2u;
    const uint32_t b_base = ((wn*32 + bprow)*TSH + bpcol) * 2u;

    for (int kt = 0; kt < kTiles; kt++) {
        if (kt + 1 < kTiles) asm volatile("cp.async.wait_group 1;");
        else                 asm volatile("cp.async.wait_group 0;");
        __syncthreads();
        if (kt + 2 < kTiles) load_stage(kt + 2, (kt + 2) % 3);

        const int buf = kt % 3;
        const uint32_t as_u32 = (uint32_t)__cvta_generic_to_shared(smh)
                                + buf*STAGE_H*2u;
        const uint32_t bs_u32 = as_u32 + 128*TSH*2u;
#pragma unroll
        for (int k16 = 0; k16 < 4; k16++) {
            unsigned af[4][4], bf[2][4];
#pragma unroll
            for (int mt = 0; mt < 4; mt++)
                LDSM_X4(af[mt], as_u32 + a_base + mt*(16u*TSH*2u) + k16*32u);
#pragma unroll
            for (int p = 0; p < 2; p++)
                LDSM_X4(bf[p], bs_u32 + b_base + p*(16u*TSH*2u) + k16*32u);
#pragma unroll
            for (int mt = 0; mt < 4; mt++) {
                MMA_F16(acc[mt][0], af[mt][0], af[mt][1], af[mt][2], af[mt][3],
                        bf[0][0], bf[0][1]);
                MMA_F16(acc[mt][1], af[mt][0], af[mt][1], af[mt][2], af[mt][3],
                        bf[0][2], bf[0][3]);
                MMA_F16(acc[mt][2], af[mt][0], af[mt][1], af[mt][2], af[mt][3],
                        bf[1][0], bf[1][1]);
                MMA_F16(acc[mt][3], af[mt][0], af[mt][1], af[mt][2], af[mt][3],
                        bf[1][2], bf[1][3]);
            }
        }
    }

    // ---- epilogue ----
#pragma unroll
    for (int mt = 0; mt < 4; mt++) {
        int row0 = bm + wm*64 + mt*16 + r8;
#pragma unroll
        for (int nt = 0; nt < 4; nt++) {
            int col0 = bn + wn*32 + nt*8 + c4*2;
            float b0 = 0.f, b1 = 0.f;
            if (!PARTIAL) { b0 = __ldg(&bias[col0]); b1 = __ldg(&bias[col0 + 1]); }
#pragma unroll
            for (int half = 0; half < 2; half++) {
                int row = row0 + half*8;
                float v0 = acc[mt][nt][half*2 + 0] + b0;
                float v1 = acc[mt][nt][half*2 + 1] + b1;
                if (GELU) { v0 = v0 * normcdff(v0); v1 = v1 * normcdff(v1); }
                if (HOUT) {
                    __half* C = (__half*)Cv;
                    *(unsigned*)&C[(size_t)row*Nc + col0] = packh2(v0, v1);
                } else {
                    float* C = (float*)Cv + (PARTIAL ? (size_t)z * M * Nc : 0);
                    *(float2*)&C[(size_t)row*Nc + col0] = make_float2(v0, v1);
                }
            }
        }
    }
}

// ------- fp16 flash attention: trans-ldmatrix V, register P ---------------
#define AQ_STR 72   // halves; 144B rows, conflict-free

__global__ __launch_bounds__(256) void attn_tc(
    const __half* __restrict__ qkv, const float* __restrict__ adj,
    __half* __restrict__ out, int bh0)
{
    extern __shared__ __half sma[];
    __half* Qs  = sma;                 // [128][72]
    __half* Kb0 = Qs + 128*AQ_STR;     // 2 x [64][72]
    __half* Vb0 = Kb0 + 2*64*AQ_STR;   // 2 x [64][72]

    const int tid  = threadIdx.x;
    const int lane = tid & 31;
    const int warp = tid >> 5;
    const int r8   = lane >> 2;
    const int c4   = lane & 3;
    const int bh   = blockIdx.y + bh0;
    const int b    = bh / Hh, h = bh % Hh;
    const int q0   = blockIdx.x * 128;
    const int qrow = (warp >> 2)*64 + (warp & 3)*16;
    const float scale = 0.125f;

    const int lrow  = ((lane >> 3) & 1) * 8 + (lane & 7);
    const int acol  = (lane >> 4) * 8;
    const int bprow = ((lane >> 4) & 1) * 8 + (lane & 7);
    const int bpcol = ((lane >> 3) & 1) * 8;
    const int vrow  = (lane & 7) + ((lane >> 3) & 1) * 8;
    const int vcol  = (lane >> 4) * 8;

    const uint32_t qs_u32 = (uint32_t)__cvta_generic_to_shared(Qs);
    uint32_t ks_u32[2] = {
        (uint32_t)__cvta_generic_to_shared(Kb0),
        (uint32_t)__cvta_generic_to_shared(Kb0 + 64*AQ_STR) };
    uint32_t vs_u32[2] = {
        (uint32_t)__cvta_generic_to_shared(Vb0),
        (uint32_t)__cvta_generic_to_shared(Vb0 + 64*AQ_STR) };
    const uint32_t q_off  = ((qrow + lrow)*AQ_STR + acol) * 2u;
    const uint32_t kp_off = (bprow*AQ_STR + bpcol) * 2u;
    const uint32_t v_off  = (vrow*AQ_STR + vcol) * 2u;

    // load Q tile: 128 rows x 64 halves, uint4 chunks
#pragma unroll
    for (int it = 0; it < 4; it++) {
        int idx = tid + it*256;
        int r = idx >> 3, d8 = (idx & 7) * 8;
        uint4 q4 = *(const uint4*)&qkv[(size_t)(b*Nseq + q0 + r)*(3*Dmod)
                                       + h*DHd + d8];
        *(uint4*)&Qs[r*AQ_STR + d8] = q4;
    }

    auto load_kv = [&](int kt, int buf) {
        const int k0 = kt*64;
        __half* kd = Kb0 + buf*64*AQ_STR;
        __half* vd = Vb0 + buf*64*AQ_STR;
#pragma unroll
        for (int i = 0; i < 2; i++) {
            int idx = tid + i*256;
            int r = idx >> 3, d8 = (idx & 7) * 8;
            size_t base = (size_t)(b*Nseq + k0 + r)*(3*Dmod) + h*DHd + d8;
            cp16((unsigned)__cvta_generic_to_shared(&kd[r*AQ_STR + d8]),
                 qkv + base + Dmod);
            cp16((unsigned)__cvta_generic_to_shared(&vd[r*AQ_STR + d8]),
                 qkv + base + 2*Dmod);
        }
        asm volatile("cp.async.commit_group;");
    };

    load_kv(0, 0);

    float m0 = -1e30f, m1 = -1e30f, l0 = 0.f, l1 = 0.f;
    float o[8][4];
#pragma unroll
    for (int nt = 0; nt < 8; nt++)
#pragma unroll
        for (int r = 0; r < 4; r++) o[nt][r] = 0.f;

    for (int kt = 0; kt < Nseq/64; kt++) {
        const int buf = kt & 1;
        asm volatile("cp.async.wait_group 0;");
        __syncthreads();
        if (kt + 1 < Nseq/64) load_kv(kt + 1, buf ^ 1);

        // ---- S = Q @ K^T ----
        float s[8][4];
#pragma unroll
        for (int nt = 0; nt < 8; nt++)
#pragma unroll
            for (int r = 0; r < 4; r++) s[nt][r] = 0.f;

#pragma unroll
        for (int k16 = 0; k16 < 4; k16++) {
            unsigned aq[4];
            LDSM_X4(aq, qs_u32 + q_off + k16*32u);
#pragma unroll
            for (int ntp = 0; ntp < 4; ntp++) {
                unsigned kb4[4];
                LDSM_X4(kb4, ks_u32[buf] + kp_off + ntp*(16u*AQ_STR*2u) + k16*32u);
                MMA_F16(s[2*ntp    ], aq[0], aq[1], aq[2], aq[3], kb4[0], kb4[1]);
                MMA_F16(s[2*ntp + 1], aq[0], aq[1], aq[2], aq[3], kb4[2], kb4[3]);
            }
        }

        // ---- scale + adjacency bias ----
        const int k0 = kt*64;
        const int qg0 = q0 + qrow + r8;
#pragma unroll
        for (int nt = 0; nt < 8; nt++) {
            int col = k0 + nt*8 + c4*2;
            float2 ad0 = *(const float2*)&adj[(size_t) qg0     *Nseq + col];
            float2 ad1 = *(const float2*)&adj[(size_t)(qg0 + 8)*Nseq + col];
            s[nt][0] = s[nt][0]*scale + ad0.x;
            s[nt][1] = s[nt][1]*scale + ad0.y;
            s[nt][2] = s[nt][2]*scale + ad1.x;
            s[nt][3] = s[nt][3]*scale + ad1.y;
        }

        // ---- online softmax ----
        float mx0 = -1e30f, mx1 = -1e30f;
#pragma unroll
        for (int nt = 0; nt < 8; nt++) {
            mx0 = fmaxf(mx0, fmaxf(s[nt][0], s[nt][1]));
            mx1 = fmaxf(mx1, fmaxf(s[nt][2], s[nt][3]));
        }
        mx0 = fmaxf(mx0, __shfl_xor_sync(0xffffffffu, mx0, 1));
        mx0 = fmaxf(mx0, __shfl_xor_sync(0xffffffffu, mx0, 2));
        mx1 = fmaxf(mx1, __shfl_xor_sync(0xffffffffu, mx1, 1));
        mx1 = fmaxf(mx1, __shfl_xor_sync(0xffffffffu, mx1, 2));
        float mn0 = fmaxf(m0, mx0), mn1 = fmaxf(m1, mx1);
        float al0 = __expf(m0 - mn0), al1 = __expf(m1 - mn1);
        float rs0 = 0.f, rs1 = 0.f;
#pragma unroll
        for (int nt = 0; nt < 8; nt++) {
            s[nt][0] = __expf(s[nt][0] - mn0);
            s[nt][1] = __expf(s[nt][1] - mn0);
            s[nt][2] = __expf(s[nt][2] - mn1);
            s[nt][3] = __expf(s[nt][3] - mn1);
            rs0 += s[nt][0] + s[nt][1];
            rs1 += s[nt][2] + s[nt][3];
        }
        rs0 += __shfl_xor_sync(0xffffffffu, rs0, 1);
        rs0 += __shfl_xor_sync(0xffffffffu, rs0, 2);
        rs1 += __shfl_xor_sync(0xffffffffu, rs1, 1);
        rs1 += __shfl_xor_sync(0xffffffffu, rs1, 2);
        l0 = l0*al0 + rs0;  l1 = l1*al1 + rs1;
        m0 = mn0;           m1 = mn1;
#pragma unroll
        for (int nt = 0; nt < 8; nt++) {
            o[nt][0] *= al0; o[nt][1] *= al0;
            o[nt][2] *= al1; o[nt][3] *= al1;
        }

        // ---- O += P @ V : P packed from registers, V via ldmatrix.trans ----
#pragma unroll
        for (int k16 = 0; k16 < 4; k16++) {
            unsigned ap0 = packh2(s[2*k16    ][0], s[2*k16    ][1]);
            unsigned ap1 = packh2(s[2*k16    ][2], s[2*k16    ][3]);
            unsigned ap2 = packh2(s[2*k16 + 1][0], s[2*k16 + 1][1]);
            unsigned ap3 = packh2(s[2*k16 + 1][2], s[2*k16 + 1][3]);
#pragma unroll
            for (int p = 0; p < 4; p++) {
                unsigned vb[4];
                LDSM_X4T(vb, vs_u32[buf] + v_off + k16*(16u*AQ_STR*2u) + p*32u);
                MMA_F16(o[2*p    ], ap0, ap1, ap2, ap3, vb[0], vb[1]);
                MMA_F16(o[2*p + 1], ap0, ap1, ap2, ap3, vb[2], vb[3]);
            }
        }
        __syncthreads();
    }

    const int qg0 = q0 + qrow + r8;
    float i0 = 1.f / l0, i1 = 1.f / l1;
#pragma unroll
    for (int nt = 0; nt < 8; nt++) {
        int col = h*DHd + nt*8 + c4*2;
        *(unsigned*)&out[(size_t)(b*Nseq + qg0    )*Dmod + col] =
            packh2(o[nt][0]*i0, o[nt][1]*i0);
        *(unsigned*)&out[(size_t)(b*Nseq + qg0 + 8)*Dmod + col] =
            packh2(o[nt][2]*i1, o[nt][3]*i1);
    }
}

// ---------------- launcher: two-half pipelined DAG ----------------
extern "C" void kernel_launch(void* const* d_in, const int* in_sizes, int n_in,
                              void* d_out, int out_size)
{
    const float* x      = (const float*)d_in[0];
    const float* adj    = (const float*)d_in[1];
    const float* ln1_g  = (const float*)d_in[2];
    const float* ln1_b  = (const float*)d_in[3];
    const float* qkv_w  = (const float*)d_in[4];
    const float* qkv_b  = (const float*)d_in[5];
    const float* proj_w = (const float*)d_in[6];
    const float* proj_b = (const float*)d_in[7];
    const float* ln2_g  = (const float*)d_in[8];
    const float* ln2_b  = (const float*)d_in[9];
    const float* fc1_w  = (const float*)d_in[10];
    const float* fc1_b  = (const float*)d_in[11];
    const float* fc2_w  = (const float*)d_in[12];
    const float* fc2_b  = (const float*)d_in[13];
    float* out = (float*)d_out;

    __half *h, *qkv, *attn, *h2, *act, *wqkvT, *wprojT, *wfc1T, *wfc2T;
    float *x1, *part;
    cudaGetSymbolAddress((void**)&h,     g_h);
    cudaGetSymbolAddress((void**)&qkv,   g_qkv);
    cudaGetSymbolAddress((void**)&attn,  g_attn);
    cudaGetSymbolAddress((void**)&x1,    g_x1);
    cudaGetSymbolAddress((void**)&h2,    g_h2);
    cudaGetSymbolAddress((void**)&act,   g_act);
    cudaGetSymbolAddress((void**)&part,  g_part);
    cudaGetSymbolAddress((void**)&wqkvT, g_wqkvT);
    cudaGetSymbolAddress((void**)&wprojT,g_wprojT);
    cudaGetSymbolAddress((void**)&wfc1T, g_wfc1T);
    cudaGetSymbolAddress((void**)&wfc2T, g_wfc2T);

    const int attn_smem = (128*AQ_STR + 2*64*AQ_STR + 2*64*AQ_STR) * 2; // 55296
    static cudaStream_t s2 = nullptr;
    static cudaEvent_t evA = nullptr, evQ = nullptr, evW = nullptr;
    static cudaEvent_t eK0 = nullptr, eK1 = nullptr, eA0 = nullptr,
                       eEnd = nullptr;
    if (!s2) {
        cudaFuncSetAttribute(gemm_tc<false,false,true>,
            cudaFuncAttributeMaxDynamicSharedMemorySize, GEMM_SMEM);
        cudaFuncSetAttribute(gemm_tc<true,false,true>,
            cudaFuncAttributeMaxDynamicSharedMemorySize, GEMM_SMEM);
        cudaFuncSetAttribute(gemm_tc<false,true,false>,
            cudaFuncAttributeMaxDynamicSharedMemorySize, GEMM_SMEM);
        cudaFuncSetAttribute(attn_tc,
            cudaFuncAttributeMaxDynamicSharedMemorySize, attn_smem);
        cudaStreamCreateWithFlags(&s2, cudaStreamNonBlocking);
        cudaEventCreateWithFlags(&evA, cudaEventDisableTiming);
        cudaEventCreateWithFlags(&evQ, cudaEventDisableTiming);
        cudaEventCreateWithFlags(&evW, cudaEventDisableTiming);
        cudaEventCreateWithFlags(&eK0, cudaEventDisableTiming);
        cudaEventCreateWithFlags(&eK1, cudaEventDisableTiming);
        cudaEventCreateWithFlags(&eA0, cudaEventDisableTiming);
        cudaEventCreateWithFlags(&eEnd, cudaEventDisableTiming);
    }

    dim3 tb(32, 8);
    const size_t off1 = (size_t)ROWS_H;

    // ---- fork: s2 does the weight transposes (fp32 -> fp16 [N][K]) ----
    cudaEventRecord(evA, 0);
    cudaStreamWaitEvent(s2, evA, 0);
    transpose32<<<dim3(3*Dmod/32, Dmod/32), tb, 0, s2>>>(qkv_w, wqkvT, Dmod, 3*Dmod);
    cudaEventRecord(evQ, s2);
    transpose32<<<dim3(Dmod/32, Dmod/32), tb, 0, s2>>>(proj_w, wprojT, Dmod, Dmod);
    transpose32<<<dim3(HID/32,  Dmod/32), tb, 0, s2>>>(fc1_w,  wfc1T, Dmod, HID);
    transpose32<<<dim3(Dmod/32, HID/32),  tb, 0, s2>>>(fc2_w,  wfc2T, HID, Dmod);
    cudaEventRecord(evW, s2);

    // ---- main stream: LN1 overlaps qkv-weight transpose ----
    ln_warp<<<ROWS/8, 256>>>(x, ln1_g, ln1_b, h);
    cudaStreamWaitEvent(0, evQ, 0);
    gemm_tc<false,false,true><<<dim3(18, 16, 1), 256, GEMM_SMEM>>>(
        h, wqkvT, qkv_b, qkv, ROWS, Dmod, 3*Dmod, Dmod);
    cudaEventRecord(eK0, 0);
    gemm_tc<false,false,true><<<dim3(18, 16, 1), 256, GEMM_SMEM>>>(
        h + off1*Dmod, wqkvT, qkv_b, qkv + off1*3*Dmod,
        ROWS, Dmod, 3*Dmod, Dmod);
    cudaEventRecord(eK1, 0);

    // ---- s2: attention halves ----
    cudaStreamWaitEvent(s2, eK0, 0);
    attn_tc<<<dim3(Nseq/128, Bsz*Hh/2), 256, attn_smem, s2>>>(qkv, adj, attn, 0);
    cudaEventRecord(eA0, s2);
    cudaStreamWaitEvent(s2, eK1, 0);
    attn_tc<<<dim3(Nseq/128, Bsz*Hh/2), 256, attn_smem, s2>>>(qkv, adj, attn,
                                                              Bsz*Hh/2);

    // ---- stream 0: MLP chain half 0 ----
    cudaStreamWaitEvent(0, eA0, 0);
    cudaStreamWaitEvent(0, evW, 0);
    gemm_tc<false,true,false><<<dim3(6, 16, 3), 256, GEMM_SMEM>>>(
        attn, wprojT, proj_b, part, ROWS, Dmod, Dmod, Dmod/3);
    reduce3_ln<<<ROWS_H/8, 256>>>(part, proj_b, x, x1, ln2_g, ln2_b, h2);
    gemm_tc<true,false,true><<<dim3(24, 16, 1), 256, GEMM_SMEM>>>(
        h2, wfc1T, fc1_b, act, ROWS, Dmod, HID, Dmod);
    gemm_tc<false,true,false><<<dim3(6, 16, 3), 256, GEMM_SMEM>>>(
        act, wfc2T, fc2_b, part, ROWS, HID, Dmod, HID/3);
    reduce3_kernel<<<ROWS_H*Dmod/4/256, 256>>>(part, fc2_b, x1, out, Dmod);

    // ---- s2: MLP chain half 1 ----
    gemm_tc<false,true,false><<<dim3(6, 16, 3), 256, GEMM_SMEM, s2>>>(
        attn + off1*Dmod, wprojT, proj_b, part + off1*Dmod,
        ROWS, Dmod, Dmod, Dmod/3);
    reduce3_ln<<<ROWS_H/8, 256, 0, s2>>>(
        part + off1*Dmod, proj_b, x + off1*Dmod, x1 + off1*Dmod,
        ln2_g, ln2_b, h2 + off1*Dmod);
    gemm_tc<true,false,true><<<dim3(24, 16, 1), 256, GEMM_SMEM, s2>>>(
        h2 + off1*Dmod, wfc1T, fc1_b, act + off1*HID,
        ROWS, Dmod, HID, Dmod);
    gemm_tc<false,true,false><<<dim3(6, 16, 3), 256, GEMM_SMEM, s2>>>(
        act + off1*HID, wfc2T, fc2_b, part + off1*Dmod,
        ROWS, HID, Dmod, HID/3);
    reduce3_kernel<<<ROWS_H*Dmod/4/256, 256, 0, s2>>>(
        part + off1*Dmod, fc2_b, x1 + off1*Dmod, out + off1*Dmod, Dmod);
    cudaEventRecord(eEnd, s2);

    // ---- join ----
    cudaStreamWaitEvent(0, eEnd, 0);
}